// round 1
// baseline (speedup 1.0000x reference)
#include <cuda_runtime.h>
#include <cstddef>

#define N_SUP 200
#define N_SMP 120
#define N_TOT 320
#define CH 64
#define EPSBN 1e-5

// ---------------- scratch (device globals; no allocation allowed) ----------
__device__ float  g_bufA[(size_t)N_TOT * CH * 84 * 84];   // ~578 MB
__device__ float  g_bufB[(size_t)N_TOT * CH * 42 * 42];   // ~145 MB
__device__ float  g_feat[(size_t)N_TOT * 1600];
__device__ double g_sums[256];        // [0..127]=sum, [128..255]=sumsq  (grp*64+c)
__device__ float  g_coefA[128];       // scale  per (grp,c)
__device__ float  g_coefB[128];       // shift  per (grp,c)
__device__ double g_volA[40];

// ---------------- gather support+sample into one contiguous batch ----------
__global__ void gather_input(const float* __restrict__ sup,
                             const float* __restrict__ smp,
                             float* __restrict__ out)
{
    size_t i = (size_t)blockIdx.x * blockDim.x + threadIdx.x;
    const size_t nsup = (size_t)N_SUP * 3 * 84 * 84;
    const size_t ntot = (size_t)N_TOT * 3 * 84 * 84;
    if (i >= ntot) return;
    out[i] = (i < nsup) ? sup[i] : smp[i - nsup];
}

// ---------------- conv 3x3 SAME + ReLU --------------------------------------
// grid: (pixel tiles, cout/16, image), block: 256
template<int CIN, int H>
__global__ void conv_relu(const float* __restrict__ in,
                          const float* __restrict__ w,
                          const float* __restrict__ bias,
                          float* __restrict__ out)
{
    constexpr int NPIX = H * H;
    constexpr int CO_PER = 16;
    __shared__ float ws[CO_PER * CIN * 9];

    int cog = blockIdx.y;
    for (int i = threadIdx.x; i < CO_PER * CIN * 9; i += blockDim.x)
        ws[i] = w[(size_t)cog * CO_PER * CIN * 9 + i];
    __syncthreads();

    int p = blockIdx.x * blockDim.x + threadIdx.x;
    if (p >= NPIX) return;
    int y = p / H, x = p % H;
    int img = blockIdx.z;
    const float* inp = in + (size_t)img * CIN * NPIX;

    float acc[CO_PER];
#pragma unroll
    for (int co = 0; co < CO_PER; co++) acc[co] = bias[cog * CO_PER + co];

    for (int ci = 0; ci < CIN; ci++) {
        const float* ic = inp + (size_t)ci * NPIX;
        const float* wc = ws + ci * 9;
#pragma unroll
        for (int dy = -1; dy <= 1; dy++) {
            int yy = y + dy;
            if (yy < 0 || yy >= H) continue;
#pragma unroll
            for (int dx = -1; dx <= 1; dx++) {
                int xx = x + dx;
                if (xx < 0 || xx >= H) continue;
                float v = __ldg(&ic[yy * H + xx]);
                int tap = (dy + 1) * 3 + (dx + 1);
#pragma unroll
                for (int co = 0; co < CO_PER; co++)
                    acc[co] = fmaf(v, wc[co * CIN * 9 + tap], acc[co]);
            }
        }
    }
    float* op = out + ((size_t)img * CH + cog * CO_PER) * NPIX + p;
#pragma unroll
    for (int co = 0; co < CO_PER; co++)
        op[(size_t)co * NPIX] = fmaxf(acc[co], 0.f);
}

// ---------------- BN batch statistics (two groups: support / sample) -------
__global__ void zero_sums(double* __restrict__ sums)
{
    if (threadIdx.x < 256) sums[threadIdx.x] = 0.0;
}

__global__ void bn_stats(const float* __restrict__ in, int NPIX,
                         double* __restrict__ sums)
{
    int c = blockIdx.x, grp = blockIdx.y, sp = blockIdx.z;
    int n0 = grp ? N_SUP : 0;
    int cnt = grp ? N_SMP : N_SUP;
    int chunk = (cnt + gridDim.z - 1) / gridDim.z;
    int a0 = n0 + sp * chunk;
    int a1 = min(n0 + cnt, a0 + chunk);

    double s = 0.0, s2 = 0.0;
    for (int n = a0; n < a1; n++) {
        const float* p = in + ((size_t)n * CH + c) * NPIX;
        for (int i = threadIdx.x; i < NPIX; i += blockDim.x) {
            float v = p[i];
            s += v;
            s2 += (double)v * v;
        }
    }
    __shared__ double sh[256];
    int tid = threadIdx.x;
    sh[tid] = s; __syncthreads();
    for (int r = 128; r > 0; r >>= 1) { if (tid < r) sh[tid] += sh[tid + r]; __syncthreads(); }
    if (tid == 0) atomicAdd(&sums[grp * 64 + c], sh[0]);
    __syncthreads();
    sh[tid] = s2; __syncthreads();
    for (int r = 128; r > 0; r >>= 1) { if (tid < r) sh[tid] += sh[tid + r]; __syncthreads(); }
    if (tid == 0) atomicAdd(&sums[128 + grp * 64 + c], sh[0]);
}

__global__ void bn_finalize(const double* __restrict__ sums,
                            const float* __restrict__ g,
                            const float* __restrict__ be,
                            int NPIX,
                            float* __restrict__ coefA,
                            float* __restrict__ coefB)
{
    int i = threadIdx.x;
    if (i >= 128) return;
    int grp = i / 64, c = i % 64;
    double cnt = (double)(grp ? N_SMP : N_SUP) * NPIX;
    double mean = sums[i] / cnt;
    double var  = sums[128 + i] / cnt - mean * mean;
    double a = (double)g[c] * rsqrt(var + EPSBN);
    coefA[i] = (float)a;
    coefB[i] = (float)((double)be[c] - mean * a);
}

// ---------------- apply BN then 2x2 maxpool (VALID) -------------------------
__global__ void bn_pool(const float* __restrict__ in,
                        const float* __restrict__ coefA,
                        const float* __restrict__ coefB,
                        float* __restrict__ out, int H)
{
    int HO = H >> 1;
    long total = (long)N_TOT * CH * HO * HO;
    long idx = (long)blockIdx.x * blockDim.x + threadIdx.x;
    if (idx >= total) return;
    int x = (int)(idx % HO);
    long t = idx / HO;
    int y = (int)(t % HO); t /= HO;
    int c = (int)(t % CH);
    int n = (int)(t / CH);
    int grp = (n >= N_SUP);
    float a = coefA[grp * 64 + c], b = coefB[grp * 64 + c];
    const float* p = in + ((size_t)n * CH + c) * H * H + (2 * y) * H + 2 * x;
    float v0 = p[0]     * a + b;
    float v1 = p[1]     * a + b;
    float v2 = p[H]     * a + b;
    float v3 = p[H + 1] * a + b;
    out[idx] = fmaxf(fmaxf(v0, v1), fmaxf(v2, v3));
}

// ---------------- simplex volumes -------------------------------------------
__device__ __forceinline__ double det_elim(double* G, int n)
{
    double det = 1.0;
    for (int k = 0; k < n; k++) {
        double piv = G[k * n + k];
        det *= piv;
        double inv = 1.0 / piv;
        for (int i = k + 1; i < n; i++) {
            double f = G[i * n + k] * inv;
            for (int j = k + 1; j < n; j++) G[i * n + j] -= f * G[k * n + j];
        }
    }
    return det;
}

__global__ void volA_kernel(const float* __restrict__ feat, double* __restrict__ volA)
{
    int bw = blockIdx.x;             // b*5 + w
    int b = bw / 5, w = bw % 5;
    const float* base = feat + ((size_t)(b * 25 + w * 5)) * 1600;

    double acc[10];
#pragma unroll
    for (int k = 0; k < 10; k++) acc[k] = 0.0;

    for (int d = threadIdx.x; d < 1600; d += blockDim.x) {
        float s0 = base[d];
        float a[4];
        a[0] = base[1600 + d] - s0;
        a[1] = base[3200 + d] - s0;
        a[2] = base[4800 + d] - s0;
        a[3] = base[6400 + d] - s0;
        int k = 0;
#pragma unroll
        for (int i = 0; i < 4; i++)
#pragma unroll
            for (int j = i; j < 4; j++)
                acc[k++] += (double)a[i] * a[j];
    }
    __shared__ double sh[128];
    __shared__ double Gp[10];
    int tid = threadIdx.x;
    for (int k = 0; k < 10; k++) {
        sh[tid] = acc[k]; __syncthreads();
        for (int r = 64; r > 0; r >>= 1) { if (tid < r) sh[tid] += sh[tid + r]; __syncthreads(); }
        if (tid == 0) Gp[k] = sh[0];
        __syncthreads();
    }
    if (tid == 0) {
        double G[16];
        int k = 0;
        for (int i = 0; i < 4; i++)
            for (int j = i; j < 4; j++) { G[i * 4 + j] = Gp[k]; G[j * 4 + i] = Gp[k]; k++; }
        volA[bw] = det_elim(G, 4);
    }
}

__global__ void volB_kernel(const float* __restrict__ feat,
                            const double* __restrict__ volA,
                            float* __restrict__ out)
{
    int bx = blockIdx.x;             // b*75 + q*5 + w
    int w = bx % 5;
    int q = (bx / 5) % 15;
    int b = bx / 75;
    const float* sm = feat + ((size_t)(N_SUP + b * 15 + q)) * 1600;
    const float* s0 = feat + ((size_t)(b * 25 + w * 5)) * 1600;

    double acc[15];
#pragma unroll
    for (int k = 0; k < 15; k++) acc[k] = 0.0;

    for (int d = threadIdx.x; d < 1600; d += blockDim.x) {
        float sv = sm[d];
        float r[5];
#pragma unroll
        for (int s = 0; s < 5; s++) r[s] = s0[(size_t)s * 1600 + d] - sv;
        int k = 0;
#pragma unroll
        for (int i = 0; i < 5; i++)
#pragma unroll
            for (int j = i; j < 5; j++)
                acc[k++] += (double)r[i] * r[j];
    }
    __shared__ double sh[128];
    __shared__ double Gp[15];
    int tid = threadIdx.x;
    for (int k = 0; k < 15; k++) {
        sh[tid] = acc[k]; __syncthreads();
        for (int r = 64; r > 0; r >>= 1) { if (tid < r) sh[tid] += sh[tid + r]; __syncthreads(); }
        if (tid == 0) Gp[k] = sh[0];
        __syncthreads();
    }
    if (tid == 0) {
        double G[25];
        int k = 0;
        for (int i = 0; i < 5; i++)
            for (int j = i; j < 5; j++) { G[i * 5 + j] = Gp[k]; G[j * 5 + i] = Gp[k]; k++; }
        double detB = det_elim(G, 5);
        out[bx] = (float)(-(detB / volA[b * 5 + w]));
    }
}

// ---------------- host orchestration ----------------------------------------
extern "C" void kernel_launch(void* const* d_in, const int* in_sizes, int n_in,
                              void* d_out, int out_size)
{
    const float* sup = (const float*)d_in[0];
    const float* smp = (const float*)d_in[2];
    const float* W[4]  = {(const float*)d_in[3],  (const float*)d_in[7],
                          (const float*)d_in[11], (const float*)d_in[15]};
    const float* Bb[4] = {(const float*)d_in[4],  (const float*)d_in[8],
                          (const float*)d_in[12], (const float*)d_in[16]};
    const float* Gg[4] = {(const float*)d_in[5],  (const float*)d_in[9],
                          (const float*)d_in[13], (const float*)d_in[17]};
    const float* Be[4] = {(const float*)d_in[6],  (const float*)d_in[10],
                          (const float*)d_in[14], (const float*)d_in[18]};
    float* out = (float*)d_out;

    float  *bufA, *bufB, *feat, *coefA, *coefB;
    double *sums, *volA;
    cudaGetSymbolAddress((void**)&bufA,  g_bufA);
    cudaGetSymbolAddress((void**)&bufB,  g_bufB);
    cudaGetSymbolAddress((void**)&feat,  g_feat);
    cudaGetSymbolAddress((void**)&sums,  g_sums);
    cudaGetSymbolAddress((void**)&coefA, g_coefA);
    cudaGetSymbolAddress((void**)&coefB, g_coefB);
    cudaGetSymbolAddress((void**)&volA,  g_volA);

    // gather input into bufB
    {
        size_t ntot = (size_t)N_TOT * 3 * 84 * 84;
        gather_input<<<(unsigned)((ntot + 255) / 256), 256>>>(sup, smp, bufB);
    }

    // ---- layer 1: 3 -> 64, 84x84 ----
    conv_relu<3, 84><<<dim3(28, 4, N_TOT), 256>>>(bufB, W[0], Bb[0], bufA);
    zero_sums<<<1, 256>>>(sums);
    bn_stats<<<dim3(64, 2, 8), 256>>>(bufA, 84 * 84, sums);
    bn_finalize<<<1, 128>>>(sums, Gg[0], Be[0], 84 * 84, coefA, coefB);
    {
        long total = (long)N_TOT * CH * 42 * 42;
        bn_pool<<<(unsigned)((total + 255) / 256), 256>>>(bufA, coefA, coefB, bufB, 84);
    }

    // ---- layer 2: 64 -> 64, 42x42 ----
    conv_relu<64, 42><<<dim3(7, 4, N_TOT), 256>>>(bufB, W[1], Bb[1], bufA);
    zero_sums<<<1, 256>>>(sums);
    bn_stats<<<dim3(64, 2, 8), 256>>>(bufA, 42 * 42, sums);
    bn_finalize<<<1, 128>>>(sums, Gg[1], Be[1], 42 * 42, coefA, coefB);
    {
        long total = (long)N_TOT * CH * 21 * 21;
        bn_pool<<<(unsigned)((total + 255) / 256), 256>>>(bufA, coefA, coefB, bufB, 42);
    }

    // ---- layer 3: 64 -> 64, 21x21 ----
    conv_relu<64, 21><<<dim3(2, 4, N_TOT), 256>>>(bufB, W[2], Bb[2], bufA);
    zero_sums<<<1, 256>>>(sums);
    bn_stats<<<dim3(64, 2, 8), 256>>>(bufA, 21 * 21, sums);
    bn_finalize<<<1, 128>>>(sums, Gg[2], Be[2], 21 * 21, coefA, coefB);
    {
        long total = (long)N_TOT * CH * 10 * 10;
        bn_pool<<<(unsigned)((total + 255) / 256), 256>>>(bufA, coefA, coefB, bufB, 21);
    }

    // ---- layer 4: 64 -> 64, 10x10 ----
    conv_relu<64, 10><<<dim3(1, 4, N_TOT), 256>>>(bufB, W[3], Bb[3], bufA);
    zero_sums<<<1, 256>>>(sums);
    bn_stats<<<dim3(64, 2, 8), 256>>>(bufA, 10 * 10, sums);
    bn_finalize<<<1, 128>>>(sums, Gg[3], Be[3], 10 * 10, coefA, coefB);
    {
        long total = (long)N_TOT * CH * 5 * 5;   // writes [n][c*25+p] == feat[n][d]
        bn_pool<<<(unsigned)((total + 255) / 256), 256>>>(bufA, coefA, coefB, feat, 10);
    }

    // ---- simplex similarities ----
    volA_kernel<<<40, 128>>>(feat, volA);
    volB_kernel<<<600, 128>>>(feat, volA, out);
}

// round 2
// speedup vs baseline: 2.2407x; 2.2407x over previous
#include <cuda_runtime.h>
#include <cstddef>

#define N_SUP 200
#define N_SMP 120
#define N_TOT 320
#define CH 64
#define EPSBN 1e-5

// ---------------- scratch (device globals; no allocation allowed) ----------
__device__ float  g_bufA[(size_t)N_TOT * CH * 84 * 84];   // ~578 MB, carved into regions
__device__ float  g_bufB[(size_t)N_TOT * CH * 42 * 42];   // ~145 MB
__device__ float  g_feat[(size_t)N_TOT * 1600];
__device__ double g_sums[256];        // [0..127]=sum, [128..255]=sumsq  (grp*64+c)
__device__ float  g_coefA[128];       // scale  per (grp,c)
__device__ float  g_coefB[128];       // shift  per (grp,c)
__device__ double g_volA[40];

// region offsets inside g_bufA (floats)
#define OFF_PMAX ((size_t)0)
#define OFF_PMIN ((size_t)40000000)
#define OFF_IN0  ((size_t)80000000)

// ---------------- f32x2 helpers ---------------------------------------------
__device__ __forceinline__ unsigned long long pk2(float lo, float hi) {
    unsigned long long r;
    asm("mov.b64 %0, {%1, %2};" : "=l"(r)
        : "r"(__float_as_uint(lo)), "r"(__float_as_uint(hi)));
    return r;
}
__device__ __forceinline__ void upk2(unsigned long long p, float& lo, float& hi) {
    unsigned a, b;
    asm("mov.b64 {%0, %1}, %2;" : "=r"(a), "=r"(b) : "l"(p));
    lo = __uint_as_float(a); hi = __uint_as_float(b);
}
__device__ __forceinline__ void fma2(unsigned long long& acc,
                                     unsigned long long w,
                                     unsigned long long v) {
    asm("fma.rn.f32x2 %0, %1, %2, %0;" : "+l"(acc) : "l"(w), "l"(v));
}

// ---------------- gather support+sample into one contiguous batch ----------
__global__ void gather_input(const float* __restrict__ sup,
                             const float* __restrict__ smp,
                             float* __restrict__ out)
{
    size_t i = (size_t)blockIdx.x * blockDim.x + threadIdx.x;
    const size_t nsup = (size_t)N_SUP * 3 * 84 * 84;
    const size_t ntot = (size_t)N_TOT * 3 * 84 * 84;
    if (i >= ntot) return;
    out[i] = (i < nsup) ? sup[i] : smp[i - nsup];
}

// ---------------- fused conv3x3 + ReLU + stats + minmax-pool ----------------
// Thread: 2x2 output pixels x 16 couts (as 8 f32x2 channel-pairs).
// Writes pooled max & pooled min; accumulates per-(grp,channel) sum/sumsq.
template<int CIN, int H, int TILE, int TPB>
__global__ void __launch_bounds__(TPB)
conv_fused(const float* __restrict__ in,
           const float* __restrict__ w,
           const float* __restrict__ bias,
           float* __restrict__ pmax,
           float* __restrict__ pmin,
           double* __restrict__ sums)
{
    constexpr int NPIX = H * H;
    constexpr int HO = H / 2;
    constexpr int TDIM = TILE / 2;
    constexpr int NACT = TDIM * TDIM;
    constexpr int TPR = (H + TILE - 1) / TILE;
    constexpr int KT = CIN * 9;

    __shared__ float ws[KT * 16];            // [ci*9+tap][co]  co contiguous
    __shared__ float sred[16][32];           // [warp][co(0..15) | co+16 for sumsq]

    const int tid = threadIdx.x;
    const int cog = blockIdx.y;
    const int img = blockIdx.z;
    const int tile = blockIdx.x;
    const int offy = (tile / TPR) * TILE;
    const int offx = (tile % TPR) * TILE;

    // stage weights transposed: ws[kt*16 + co] = w[(cog*16+co)*KT + kt]
    for (int i = tid; i < KT * 16; i += TPB) {
        int kt = i >> 4, co = i & 15;
        ws[i] = w[(size_t)(cog * 16 + co) * KT + kt];
    }
    __syncthreads();

    const int tyy = tid / TDIM, txx = tid % TDIM;
    const bool active = tid < NACT;
    const int gy0 = offy + 2 * tyy;
    const int gx0 = offx + 2 * txx;

    bool rv[4], cv[4];
#pragma unroll
    for (int r = 0; r < 4; r++) { int yy = gy0 - 1 + r; rv[r] = active && yy >= 0 && yy < H; }
#pragma unroll
    for (int c = 0; c < 4; c++) { int xx = gx0 - 1 + c; cv[c] = active && xx >= 0 && xx < H; }

    const float* inp = in + (size_t)img * CIN * NPIX + (long)(gy0 - 1) * H + (gx0 - 1);

    unsigned long long acc[8][4];
#pragma unroll
    for (int cp = 0; cp < 8; cp++) {
        unsigned long long bp = pk2(bias[cog * 16 + 2 * cp], bias[cog * 16 + 2 * cp + 1]);
#pragma unroll
        for (int px = 0; px < 4; px++) acc[cp][px] = bp;
    }

    for (int ci = 0; ci < CIN; ci++) {
        const float* ic = inp + (size_t)ci * NPIX;
        float iv[4][4];
#pragma unroll
        for (int r = 0; r < 4; r++)
#pragma unroll
            for (int c = 0; c < 4; c++)
                iv[r][c] = (rv[r] && cv[c]) ? __ldg(ic + r * H + c) : 0.f;

        const float* wk = ws + ci * 9 * 16;
#pragma unroll
        for (int ky = 0; ky < 3; ky++)
#pragma unroll
        for (int kx = 0; kx < 3; kx++) {
            unsigned long long v[4];
#pragma unroll
            for (int py = 0; py < 2; py++)
#pragma unroll
            for (int pxx = 0; pxx < 2; pxx++) {
                float f = iv[py + ky][pxx + kx];
                v[py * 2 + pxx] = pk2(f, f);
            }
            const unsigned long long* wp =
                (const unsigned long long*)(wk + (ky * 3 + kx) * 16);
#pragma unroll
            for (int cp = 0; cp < 8; cp++) {
                unsigned long long wpr = wp[cp];
#pragma unroll
                for (int px = 0; px < 4; px++)
                    fma2(acc[cp][px], wpr, v[px]);
            }
        }
    }

    // per-pixel validity for stats; pool cell valid iff ph<HO && pw<HO
    bool pv[4];
#pragma unroll
    for (int py = 0; py < 2; py++)
#pragma unroll
        for (int pxx = 0; pxx < 2; pxx++)
            pv[py * 2 + pxx] = active && (gy0 + py) < H && (gx0 + pxx) < H;

    const int ph = gy0 >> 1, pw = gx0 >> 1;
    const bool wr = active && ph < HO && pw < HO;
    const int grp = (img >= N_SUP);
    const int wid = tid >> 5, lid = tid & 31;
    constexpr int NW = TPB / 32;

    float* pmax_b = pmax + ((size_t)img * CH + cog * 16) * (HO * HO) + ph * HO + pw;
    float* pmin_b = pmin + ((size_t)img * CH + cog * 16) * (HO * HO) + ph * HO + pw;

#pragma unroll
    for (int cp = 0; cp < 8; cp++) {
#pragma unroll
        for (int j = 0; j < 2; j++) {
            float r0, r1, r2, r3, t;
            upk2(acc[cp][0], r0, t); if (j) r0 = t;
            upk2(acc[cp][1], r1, t); if (j) r1 = t;
            upk2(acc[cp][2], r2, t); if (j) r2 = t;
            upk2(acc[cp][3], r3, t); if (j) r3 = t;
            r0 = fmaxf(r0, 0.f); r1 = fmaxf(r1, 0.f);
            r2 = fmaxf(r2, 0.f); r3 = fmaxf(r3, 0.f);

            float s0 = pv[0] ? r0 : 0.f, s1 = pv[1] ? r1 : 0.f;
            float s2 = pv[2] ? r2 : 0.f, s3 = pv[3] ? r3 : 0.f;
            float s = s0 + s1 + s2 + s3;
            float q = s0 * s0 + s1 * s1 + s2 * s2 + s3 * s3;
#pragma unroll
            for (int o = 16; o; o >>= 1) {
                s += __shfl_xor_sync(0xffffffffu, s, o);
                q += __shfl_xor_sync(0xffffffffu, q, o);
            }
            int co = cp * 2 + j;
            if (lid == 0) { sred[wid][co] = s; sred[wid][co + 16] = q; }

            if (wr) {
                float mx = fmaxf(fmaxf(r0, r1), fmaxf(r2, r3));
                float mn = fminf(fminf(r0, r1), fminf(r2, r3));
                pmax_b[(size_t)co * HO * HO] = mx;
                pmin_b[(size_t)co * HO * HO] = mn;
            }
        }
    }
    __syncthreads();

    if (tid < 32) {
        int co = tid & 15, isq = tid >> 4;
        float acc2 = 0.f;
#pragma unroll
        for (int ww = 0; ww < NW; ww++) acc2 += sred[ww][co + isq * 16];
        atomicAdd(&sums[isq * 128 + grp * 64 + cog * 16 + co], (double)acc2);
    }
}

// ---------------- BN stats zero / finalize ----------------------------------
__global__ void zero_sums(double* __restrict__ sums)
{
    if (threadIdx.x < 256) sums[threadIdx.x] = 0.0;
}

__global__ void bn_finalize(const double* __restrict__ sums,
                            const float* __restrict__ g,
                            const float* __restrict__ be,
                            int NPIX,
                            float* __restrict__ coefA,
                            float* __restrict__ coefB)
{
    int i = threadIdx.x;
    if (i >= 128) return;
    int grp = i / 64, c = i % 64;
    double cnt = (double)(grp ? N_SMP : N_SUP) * NPIX;
    double mean = sums[i] / cnt;
    double var  = sums[128 + i] / cnt - mean * mean;
    double a = (double)g[c] * rsqrt(var + EPSBN);
    coefA[i] = (float)a;
    coefB[i] = (float)((double)be[c] - mean * a);
}

// ---------------- pick pooled value and apply affine BN ---------------------
__global__ void bn_apply(const float* __restrict__ pmax,
                         const float* __restrict__ pmin,
                         const float* __restrict__ coefA,
                         const float* __restrict__ coefB,
                         float* __restrict__ out,
                         int plane, long total)
{
    long idx = (long)blockIdx.x * blockDim.x + threadIdx.x;
    if (idx >= total) return;
    int c = (int)((idx / plane) % CH);
    int n = (int)(idx / ((long)plane * CH));
    int grp = (n >= N_SUP);
    float a = coefA[grp * 64 + c], b = coefB[grp * 64 + c];
    float m = (a > 0.f) ? pmax[idx] : pmin[idx];
    out[idx] = fmaf(m, a, b);
}

// ---------------- simplex volumes -------------------------------------------
__device__ __forceinline__ double det_elim(double* G, int n)
{
    double det = 1.0;
    for (int k = 0; k < n; k++) {
        double piv = G[k * n + k];
        det *= piv;
        double inv = 1.0 / piv;
        for (int i = k + 1; i < n; i++) {
            double f = G[i * n + k] * inv;
            for (int j = k + 1; j < n; j++) G[i * n + j] -= f * G[k * n + j];
        }
    }
    return det;
}

__global__ void volA_kernel(const float* __restrict__ feat, double* __restrict__ volA)
{
    int bw = blockIdx.x;             // b*5 + w
    int b = bw / 5, w = bw % 5;
    const float* base = feat + ((size_t)(b * 25 + w * 5)) * 1600;

    double acc[10];
#pragma unroll
    for (int k = 0; k < 10; k++) acc[k] = 0.0;

    for (int d = threadIdx.x; d < 1600; d += blockDim.x) {
        float s0 = base[d];
        float a[4];
        a[0] = base[1600 + d] - s0;
        a[1] = base[3200 + d] - s0;
        a[2] = base[4800 + d] - s0;
        a[3] = base[6400 + d] - s0;
        int k = 0;
#pragma unroll
        for (int i = 0; i < 4; i++)
#pragma unroll
            for (int j = i; j < 4; j++)
                acc[k++] += (double)a[i] * a[j];
    }
    __shared__ double sh[128];
    __shared__ double Gp[10];
    int tid = threadIdx.x;
    for (int k = 0; k < 10; k++) {
        sh[tid] = acc[k]; __syncthreads();
        for (int r = 64; r > 0; r >>= 1) { if (tid < r) sh[tid] += sh[tid + r]; __syncthreads(); }
        if (tid == 0) Gp[k] = sh[0];
        __syncthreads();
    }
    if (tid == 0) {
        double G[16];
        int k = 0;
        for (int i = 0; i < 4; i++)
            for (int j = i; j < 4; j++) { G[i * 4 + j] = Gp[k]; G[j * 4 + i] = Gp[k]; k++; }
        volA[bw] = det_elim(G, 4);
    }
}

__global__ void volB_kernel(const float* __restrict__ feat,
                            const double* __restrict__ volA,
                            float* __restrict__ out)
{
    int bx = blockIdx.x;             // b*75 + q*5 + w
    int w = bx % 5;
    int q = (bx / 5) % 15;
    int b = bx / 75;
    const float* sm = feat + ((size_t)(N_SUP + b * 15 + q)) * 1600;
    const float* s0 = feat + ((size_t)(b * 25 + w * 5)) * 1600;

    double acc[15];
#pragma unroll
    for (int k = 0; k < 15; k++) acc[k] = 0.0;

    for (int d = threadIdx.x; d < 1600; d += blockDim.x) {
        float sv = sm[d];
        float r[5];
#pragma unroll
        for (int s = 0; s < 5; s++) r[s] = s0[(size_t)s * 1600 + d] - sv;
        int k = 0;
#pragma unroll
        for (int i = 0; i < 5; i++)
#pragma unroll
            for (int j = i; j < 5; j++)
                acc[k++] += (double)r[i] * r[j];
    }
    __shared__ double sh[128];
    __shared__ double Gp[15];
    int tid = threadIdx.x;
    for (int k = 0; k < 15; k++) {
        sh[tid] = acc[k]; __syncthreads();
        for (int r = 64; r > 0; r >>= 1) { if (tid < r) sh[tid] += sh[tid + r]; __syncthreads(); }
        if (tid == 0) Gp[k] = sh[0];
        __syncthreads();
    }
    if (tid == 0) {
        double G[25];
        int k = 0;
        for (int i = 0; i < 5; i++)
            for (int j = i; j < 5; j++) { G[i * 5 + j] = Gp[k]; G[j * 5 + i] = Gp[k]; k++; }
        double detB = det_elim(G, 5);
        out[bx] = (float)(-(detB / volA[b * 5 + w]));
    }
}

// ---------------- host orchestration ----------------------------------------
extern "C" void kernel_launch(void* const* d_in, const int* in_sizes, int n_in,
                              void* d_out, int out_size)
{
    const float* sup = (const float*)d_in[0];
    const float* smp = (const float*)d_in[2];
    const float* W[4]  = {(const float*)d_in[3],  (const float*)d_in[7],
                          (const float*)d_in[11], (const float*)d_in[15]};
    const float* Bb[4] = {(const float*)d_in[4],  (const float*)d_in[8],
                          (const float*)d_in[12], (const float*)d_in[16]};
    const float* Gg[4] = {(const float*)d_in[5],  (const float*)d_in[9],
                          (const float*)d_in[13], (const float*)d_in[17]};
    const float* Be[4] = {(const float*)d_in[6],  (const float*)d_in[10],
                          (const float*)d_in[14], (const float*)d_in[18]};
    float* out = (float*)d_out;

    float  *bufA, *bufB, *feat, *coefA, *coefB;
    double *sums, *volA;
    cudaGetSymbolAddress((void**)&bufA,  g_bufA);
    cudaGetSymbolAddress((void**)&bufB,  g_bufB);
    cudaGetSymbolAddress((void**)&feat,  g_feat);
    cudaGetSymbolAddress((void**)&sums,  g_sums);
    cudaGetSymbolAddress((void**)&coefA, g_coefA);
    cudaGetSymbolAddress((void**)&coefB, g_coefB);
    cudaGetSymbolAddress((void**)&volA,  g_volA);

    float* pmax = bufA + OFF_PMAX;
    float* pmin = bufA + OFF_PMIN;
    float* in0  = bufA + OFF_IN0;

    // gather input
    {
        size_t ntot = (size_t)N_TOT * 3 * 84 * 84;
        gather_input<<<(unsigned)((ntot + 255) / 256), 256>>>(sup, smp, in0);
    }

    // ---- layer 1: 3 -> 64, 84x84 -> pooled 42x42 ----
    zero_sums<<<1, 256>>>(sums);
    conv_fused<3, 84, 42, 448><<<dim3(4, 4, N_TOT), 448>>>(in0, W[0], Bb[0], pmax, pmin, sums);
    bn_finalize<<<1, 128>>>(sums, Gg[0], Be[0], 84 * 84, coefA, coefB);
    {
        long total = (long)N_TOT * CH * 42 * 42;
        bn_apply<<<(unsigned)((total + 255) / 256), 256>>>(pmax, pmin, coefA, coefB, bufB, 42 * 42, total);
    }

    // ---- layer 2: 64 -> 64, 42x42 -> pooled 21x21 ----
    zero_sums<<<1, 256>>>(sums);
    conv_fused<64, 42, 42, 448><<<dim3(1, 4, N_TOT), 448>>>(bufB, W[1], Bb[1], pmax, pmin, sums);
    bn_finalize<<<1, 128>>>(sums, Gg[1], Be[1], 42 * 42, coefA, coefB);
    {
        long total = (long)N_TOT * CH * 21 * 21;
        bn_apply<<<(unsigned)((total + 255) / 256), 256>>>(pmax, pmin, coefA, coefB, bufB, 21 * 21, total);
    }

    // ---- layer 3: 64 -> 64, 21x21 -> pooled 10x10 ----
    zero_sums<<<1, 256>>>(sums);
    conv_fused<64, 21, 22, 128><<<dim3(1, 4, N_TOT), 128>>>(bufB, W[2], Bb[2], pmax, pmin, sums);
    bn_finalize<<<1, 128>>>(sums, Gg[2], Be[2], 21 * 21, coefA, coefB);
    {
        long total = (long)N_TOT * CH * 10 * 10;
        bn_apply<<<(unsigned)((total + 255) / 256), 256>>>(pmax, pmin, coefA, coefB, bufB, 10 * 10, total);
    }

    // ---- layer 4: 64 -> 64, 10x10 -> pooled 5x5 (features) ----
    zero_sums<<<1, 256>>>(sums);
    conv_fused<64, 10, 10, 32><<<dim3(1, 4, N_TOT), 32>>>(bufB, W[3], Bb[3], pmax, pmin, sums);
    bn_finalize<<<1, 128>>>(sums, Gg[3], Be[3], 10 * 10, coefA, coefB);
    {
        long total = (long)N_TOT * CH * 5 * 5;
        bn_apply<<<(unsigned)((total + 255) / 256), 256>>>(pmax, pmin, coefA, coefB, feat, 5 * 5, total);
    }

    // ---- simplex similarities ----
    volA_kernel<<<40, 128>>>(feat, volA);
    volB_kernel<<<600, 128>>>(feat, volA, out);
}

// round 4
// speedup vs baseline: 2.4486x; 1.0928x over previous
#include <cuda_runtime.h>
#include <cstddef>

#define N_SUP 200
#define N_SMP 120
#define N_TOT 320
#define CH 64
#define EPSBN 1e-5

// ---------------- scratch (device globals; no allocation allowed) ----------
__device__ float  g_bufA[(size_t)N_TOT * CH * 84 * 84];   // ~578 MB, carved into regions
__device__ float  g_bufB[(size_t)N_TOT * CH * 42 * 42];   // ~145 MB
__device__ float  g_feat[(size_t)N_TOT * 1600];
__device__ double g_sums[256];        // [0..127]=sum, [128..255]=sumsq  (grp*64+c)
__device__ float  g_coefA[128];
__device__ float  g_coefB[128];
__device__ double g_volA[40];

// region offsets inside g_bufA (floats)
#define OFF_PMAX ((size_t)0)
#define OFF_PMIN ((size_t)40000000)
#define OFF_IN0  ((size_t)80000000)

// ---------------- f32x2 helpers ---------------------------------------------
__device__ __forceinline__ unsigned long long pk2(float lo, float hi) {
    unsigned long long r;
    asm("mov.b64 %0, {%1, %2};" : "=l"(r)
        : "r"(__float_as_uint(lo)), "r"(__float_as_uint(hi)));
    return r;
}
__device__ __forceinline__ void upk2(unsigned long long p, float& lo, float& hi) {
    unsigned a, b;
    asm("mov.b64 {%0, %1}, %2;" : "=r"(a), "=r"(b) : "l"(p));
    lo = __uint_as_float(a); hi = __uint_as_float(b);
}
__device__ __forceinline__ void fma2(unsigned long long& acc,
                                     unsigned long long w,
                                     unsigned long long v) {
    asm("fma.rn.f32x2 %0, %1, %2, %0;" : "+l"(acc) : "l"(w), "l"(v));
}

// ---------------- gather support+sample into one contiguous batch ----------
__global__ void gather_input(const float* __restrict__ sup,
                             const float* __restrict__ smp,
                             float* __restrict__ out)
{
    size_t i = (size_t)blockIdx.x * blockDim.x + threadIdx.x;
    const size_t nsup = (size_t)N_SUP * 3 * 84 * 84;
    const size_t ntot = (size_t)N_TOT * 3 * 84 * 84;
    if (i >= ntot) return;
    out[i] = (i < nsup) ? sup[i] : smp[i - nsup];
}

// ---------------- fused conv3x3 + ReLU + stats + minmax-pool ----------------
// Thread: 2x2 output pixels x 8 couts (4 f32x2 channel-pairs)  -> 64 acc regs.
// Block covers TY pool-rows x TX pool-cols; grid = (yTiles, 8 cogroups, img).
template<int CIN, int H, int TY, int TX, int TPB, int MINB>
__global__ void __launch_bounds__(TPB, MINB)
conv_fused(const float* __restrict__ in,
           const float* __restrict__ w,
           const float* __restrict__ bias,
           float* __restrict__ pmax,
           float* __restrict__ pmin,
           double* __restrict__ sums)
{
    constexpr int NPIX = H * H;
    constexpr int HO = H / 2;
    constexpr int NACT = TY * TX;
    constexpr int KT = CIN * 9;
    constexpr int NW = TPB / 32;

    __shared__ float ws[KT * 8];             // [kt][co]  co contiguous (8)
    __shared__ float sred[NW][16];

    const int tid = threadIdx.x;
    const int cog = blockIdx.y;
    const int img = blockIdx.z;

    // stage weights: coalesced LDG (consecutive kt per thread-run), scattered STS
    for (int i = tid; i < KT * 8; i += TPB) {
        int co = i / KT, kt = i - co * KT;
        ws[kt * 8 + co] = w[(size_t)(cog * 8 + co) * KT + kt];
    }
    __syncthreads();

    const int ty = tid / TX, tx = tid % TX;
    const int py0 = blockIdx.x * TY + ty;    // pool-row index (may hit odd edge)
    const int gy0 = 2 * py0;
    const int gx0 = 2 * tx;
    const bool active = (tid < NACT) && (gy0 < H);

    bool rv[4], cv[4];
#pragma unroll
    for (int r = 0; r < 4; r++) { int yy = gy0 - 1 + r; rv[r] = active && yy >= 0 && yy < H; }
#pragma unroll
    for (int c = 0; c < 4; c++) { int xx = gx0 - 1 + c; cv[c] = active && xx >= 0 && xx < H; }

    const float* inp = in + (size_t)img * CIN * NPIX + (long)(gy0 - 1) * H + (gx0 - 1);

    unsigned long long acc[4][4];
#pragma unroll
    for (int cp = 0; cp < 4; cp++) {
        unsigned long long bp = pk2(bias[cog * 8 + 2 * cp], bias[cog * 8 + 2 * cp + 1]);
#pragma unroll
        for (int px = 0; px < 4; px++) acc[cp][px] = bp;
    }

    for (int ci = 0; ci < CIN; ci++) {
        const float* ic = inp + (size_t)ci * NPIX;
        float iv[4][4];
#pragma unroll
        for (int r = 0; r < 4; r++)
#pragma unroll
            for (int c = 0; c < 4; c++)
                iv[r][c] = (rv[r] && cv[c]) ? __ldg(ic + r * H + c) : 0.f;

        const float* wk = ws + ci * 9 * 8;
#pragma unroll
        for (int ky = 0; ky < 3; ky++)
#pragma unroll
        for (int kx = 0; kx < 3; kx++) {
            unsigned long long v[4];
#pragma unroll
            for (int py = 0; py < 2; py++)
#pragma unroll
            for (int pxx = 0; pxx < 2; pxx++) {
                float f = iv[py + ky][pxx + kx];
                v[py * 2 + pxx] = pk2(f, f);
            }
            const unsigned long long* wp =
                (const unsigned long long*)(wk + (ky * 3 + kx) * 8);
#pragma unroll
            for (int cp = 0; cp < 4; cp++) {
                unsigned long long wpr = wp[cp];
#pragma unroll
                for (int px = 0; px < 4; px++)
                    fma2(acc[cp][px], wpr, v[px]);
            }
        }
    }

    bool pv[4];
#pragma unroll
    for (int py = 0; py < 2; py++)
#pragma unroll
        for (int pxx = 0; pxx < 2; pxx++)
            pv[py * 2 + pxx] = active && (gy0 + py) < H && (gx0 + pxx) < H;

    const bool wr = active && py0 < HO && tx < HO;
    const int grp = (img >= N_SUP);
    const int wid = tid >> 5, lid = tid & 31;

    float* pmax_b = pmax + ((size_t)img * CH + cog * 8) * (HO * HO) + py0 * HO + tx;
    float* pmin_b = pmin + ((size_t)img * CH + cog * 8) * (HO * HO) + py0 * HO + tx;

#pragma unroll
    for (int cp = 0; cp < 4; cp++) {
#pragma unroll
        for (int j = 0; j < 2; j++) {
            float r0, r1, r2, r3, t;
            upk2(acc[cp][0], r0, t); if (j) r0 = t;
            upk2(acc[cp][1], r1, t); if (j) r1 = t;
            upk2(acc[cp][2], r2, t); if (j) r2 = t;
            upk2(acc[cp][3], r3, t); if (j) r3 = t;
            r0 = fmaxf(r0, 0.f); r1 = fmaxf(r1, 0.f);
            r2 = fmaxf(r2, 0.f); r3 = fmaxf(r3, 0.f);

            float s0 = pv[0] ? r0 : 0.f, s1 = pv[1] ? r1 : 0.f;
            float s2 = pv[2] ? r2 : 0.f, s3 = pv[3] ? r3 : 0.f;
            float s = s0 + s1 + s2 + s3;
            float q = s0 * s0 + s1 * s1 + s2 * s2 + s3 * s3;
#pragma unroll
            for (int o = 16; o; o >>= 1) {
                s += __shfl_xor_sync(0xffffffffu, s, o);
                q += __shfl_xor_sync(0xffffffffu, q, o);
            }
            int co = cp * 2 + j;
            if (lid == 0) { sred[wid][co] = s; sred[wid][co + 8] = q; }

            if (wr) {
                float mx = fmaxf(fmaxf(r0, r1), fmaxf(r2, r3));
                float mn = fminf(fminf(r0, r1), fminf(r2, r3));
                pmax_b[(size_t)co * HO * HO] = mx;
                pmin_b[(size_t)co * HO * HO] = mn;
            }
        }
    }
    __syncthreads();

    if (tid < 16) {
        int co = tid & 7, isq = tid >> 3;
        float acc2 = 0.f;
#pragma unroll
        for (int ww = 0; ww < NW; ww++) acc2 += sred[ww][co + isq * 8];
        atomicAdd(&sums[isq * 128 + grp * 64 + cog * 8 + co], (double)acc2);
    }
}

// ---------------- BN stats zero / finalize ----------------------------------
__global__ void zero_sums(double* __restrict__ sums)
{
    if (threadIdx.x < 256) sums[threadIdx.x] = 0.0;
}

__global__ void bn_finalize(const double* __restrict__ sums,
                            const float* __restrict__ g,
                            const float* __restrict__ be,
                            int NPIX,
                            float* __restrict__ coefA,
                            float* __restrict__ coefB)
{
    int i = threadIdx.x;
    if (i >= 128) return;
    int grp = i / 64, c = i % 64;
    double cnt = (double)(grp ? N_SMP : N_SUP) * NPIX;
    double mean = sums[i] / cnt;
    double var  = sums[128 + i] / cnt - mean * mean;
    double a = (double)g[c] * rsqrt(var + EPSBN);
    coefA[i] = (float)a;
    coefB[i] = (float)((double)be[c] - mean * a);
}

// ---------------- pick pooled value and apply affine BN ---------------------
__global__ void bn_apply(const float* __restrict__ pmax,
                         const float* __restrict__ pmin,
                         const float* __restrict__ coefA,
                         const float* __restrict__ coefB,
                         float* __restrict__ out,
                         int plane, long total)
{
    long idx = (long)blockIdx.x * blockDim.x + threadIdx.x;
    if (idx >= total) return;
    int c = (int)((idx / plane) % CH);
    int n = (int)(idx / ((long)plane * CH));
    int grp = (n >= N_SUP);
    float a = coefA[grp * 64 + c], b = coefB[grp * 64 + c];
    float m = (a > 0.f) ? pmax[idx] : pmin[idx];
    out[idx] = fmaf(m, a, b);
}

// ---------------- simplex volumes -------------------------------------------
__device__ __forceinline__ double det_elim(double* G, int n)
{
    double det = 1.0;
    for (int k = 0; k < n; k++) {
        double piv = G[k * n + k];
        det *= piv;
        double inv = 1.0 / piv;
        for (int i = k + 1; i < n; i++) {
            double f = G[i * n + k] * inv;
            for (int j = k + 1; j < n; j++) G[i * n + j] -= f * G[k * n + j];
        }
    }
    return det;
}

__global__ void volA_kernel(const float* __restrict__ feat, double* __restrict__ volA)
{
    int bw = blockIdx.x;             // b*5 + w
    int b = bw / 5, w = bw % 5;
    const float* base = feat + ((size_t)(b * 25 + w * 5)) * 1600;

    double acc[10];
#pragma unroll
    for (int k = 0; k < 10; k++) acc[k] = 0.0;

    for (int d = threadIdx.x; d < 1600; d += blockDim.x) {
        float s0 = base[d];
        float a[4];
        a[0] = base[1600 + d] - s0;
        a[1] = base[3200 + d] - s0;
        a[2] = base[4800 + d] - s0;
        a[3] = base[6400 + d] - s0;
        int k = 0;
#pragma unroll
        for (int i = 0; i < 4; i++)
#pragma unroll
            for (int j = i; j < 4; j++)
                acc[k++] += (double)a[i] * a[j];
    }
    __shared__ double sh[128];
    __shared__ double Gp[10];
    int tid = threadIdx.x;
    for (int k = 0; k < 10; k++) {
        sh[tid] = acc[k]; __syncthreads();
        for (int r = 64; r > 0; r >>= 1) { if (tid < r) sh[tid] += sh[tid + r]; __syncthreads(); }
        if (tid == 0) Gp[k] = sh[0];
        __syncthreads();
    }
    if (tid == 0) {
        double G[16];
        int k = 0;
        for (int i = 0; i < 4; i++)
            for (int j = i; j < 4; j++) { G[i * 4 + j] = Gp[k]; G[j * 4 + i] = Gp[k]; k++; }
        volA[bw] = det_elim(G, 4);
    }
}

__global__ void volB_kernel(const float* __restrict__ feat,
                            const double* __restrict__ volA,
                            float* __restrict__ out)
{
    int bx = blockIdx.x;             // b*75 + q*5 + w
    int w = bx % 5;
    int q = (bx / 5) % 15;
    int b = bx / 75;
    const float* sm = feat + ((size_t)(N_SUP + b * 15 + q)) * 1600;
    const float* s0 = feat + ((size_t)(b * 25 + w * 5)) * 1600;

    double acc[15];
#pragma unroll
    for (int k = 0; k < 15; k++) acc[k] = 0.0;

    for (int d = threadIdx.x; d < 1600; d += blockDim.x) {
        float sv = sm[d];
        float r[5];
#pragma unroll
        for (int s = 0; s < 5; s++) r[s] = s0[(size_t)s * 1600 + d] - sv;
        int k = 0;
#pragma unroll
        for (int i = 0; i < 5; i++)
#pragma unroll
            for (int j = i; j < 5; j++)
                acc[k++] += (double)r[i] * r[j];
    }
    __shared__ double sh[128];
    __shared__ double Gp[15];
    int tid = threadIdx.x;
    for (int k = 0; k < 15; k++) {
        sh[tid] = acc[k]; __syncthreads();
        for (int r = 64; r > 0; r >>= 1) { if (tid < r) sh[tid] += sh[tid + r]; __syncthreads(); }
        if (tid == 0) Gp[k] = sh[0];
        __syncthreads();
    }
    if (tid == 0) {
        double G[25];
        int k = 0;
        for (int i = 0; i < 5; i++)
            for (int j = i; j < 5; j++) { G[i * 5 + j] = Gp[k]; G[j * 5 + i] = Gp[k]; k++; }
        double detB = det_elim(G, 5);
        out[bx] = (float)(-(detB / volA[b * 5 + w]));
    }
}

// ---------------- host orchestration ----------------------------------------
extern "C" void kernel_launch(void* const* d_in, const int* in_sizes, int n_in,
                              void* d_out, int out_size)
{
    const float* sup = (const float*)d_in[0];
    const float* smp = (const float*)d_in[2];
    const float* W[4]  = {(const float*)d_in[3],  (const float*)d_in[7],
                          (const float*)d_in[11], (const float*)d_in[15]};
    const float* Bb[4] = {(const float*)d_in[4],  (const float*)d_in[8],
                          (const float*)d_in[12], (const float*)d_in[16]};
    const float* Gg[4] = {(const float*)d_in[5],  (const float*)d_in[9],
                          (const float*)d_in[13], (const float*)d_in[17]};
    const float* Be[4] = {(const float*)d_in[6],  (const float*)d_in[10],
                          (const float*)d_in[14], (const float*)d_in[18]};
    float* out = (float*)d_out;

    float  *bufA, *bufB, *feat, *coefA, *coefB;
    double *sums, *volA;
    cudaGetSymbolAddress((void**)&bufA,  g_bufA);
    cudaGetSymbolAddress((void**)&bufB,  g_bufB);
    cudaGetSymbolAddress((void**)&feat,  g_feat);
    cudaGetSymbolAddress((void**)&sums,  g_sums);
    cudaGetSymbolAddress((void**)&coefA, g_coefA);
    cudaGetSymbolAddress((void**)&coefB, g_coefB);
    cudaGetSymbolAddress((void**)&volA,  g_volA);

    float* pmax = bufA + OFF_PMAX;
    float* pmin = bufA + OFF_PMIN;
    float* in0  = bufA + OFF_IN0;

    // gather input
    {
        size_t ntot = (size_t)N_TOT * 3 * 84 * 84;
        gather_input<<<(unsigned)((ntot + 255) / 256), 256>>>(sup, smp, in0);
    }

    // ---- layer 1: 3 -> 64, 84x84 -> pooled 42x42 ----
    zero_sums<<<1, 256>>>(sums);
    conv_fused<3, 84, 6, 42, 256, 2><<<dim3(7, 8, N_TOT), 256>>>(in0, W[0], Bb[0], pmax, pmin, sums);
    bn_finalize<<<1, 128>>>(sums, Gg[0], Be[0], 84 * 84, coefA, coefB);
    {
        long total = (long)N_TOT * CH * 42 * 42;
        bn_apply<<<(unsigned)((total + 255) / 256), 256>>>(pmax, pmin, coefA, coefB, bufB, 42 * 42, total);
    }

    // ---- layer 2: 64 -> 64, 42x42 -> pooled 21x21 ----
    zero_sums<<<1, 256>>>(sums);
    conv_fused<64, 42, 11, 21, 256, 2><<<dim3(2, 8, N_TOT), 256>>>(bufB, W[1], Bb[1], pmax, pmin, sums);
    bn_finalize<<<1, 128>>>(sums, Gg[1], Be[1], 42 * 42, coefA, coefB);
    {
        long total = (long)N_TOT * CH * 21 * 21;
        bn_apply<<<(unsigned)((total + 255) / 256), 256>>>(pmax, pmin, coefA, coefB, bufB, 21 * 21, total);
    }

    // ---- layer 3: 64 -> 64, 21x21 -> pooled 10x10 ----
    zero_sums<<<1, 256>>>(sums);
    conv_fused<64, 21, 11, 11, 128, 4><<<dim3(1, 8, N_TOT), 128>>>(bufB, W[2], Bb[2], pmax, pmin, sums);
    bn_finalize<<<1, 128>>>(sums, Gg[2], Be[2], 21 * 21, coefA, coefB);
    {
        long total = (long)N_TOT * CH * 10 * 10;
        bn_apply<<<(unsigned)((total + 255) / 256), 256>>>(pmax, pmin, coefA, coefB, bufB, 10 * 10, total);
    }

    // ---- layer 4: 64 -> 64, 10x10 -> pooled 5x5 (features) ----
    zero_sums<<<1, 256>>>(sums);
    conv_fused<64, 10, 5, 5, 32, 8><<<dim3(1, 8, N_TOT), 32>>>(bufB, W[3], Bb[3], pmax, pmin, sums);
    bn_finalize<<<1, 128>>>(sums, Gg[3], Be[3], 10 * 10, coefA, coefB);
    {
        long total = (long)N_TOT * CH * 5 * 5;
        bn_apply<<<(unsigned)((total + 255) / 256), 256>>>(pmax, pmin, coefA, coefB, feat, 5 * 5, total);
    }

    // ---- simplex similarities ----
    volA_kernel<<<40, 128>>>(feat, volA);
    volB_kernel<<<600, 128>>>(feat, volA, out);
}

// round 5
// speedup vs baseline: 2.5060x; 1.0235x over previous
#include <cuda_runtime.h>
#include <cstddef>

#define N_SUP 200
#define N_SMP 120
#define N_TOT 320
#define CH 64
#define EPSBN 1e-5

// ---------------- scratch (device globals; no allocation allowed) ----------
__device__ float  g_bufA[(size_t)N_TOT * CH * 84 * 84];   // carved into pmax/pmin
__device__ float  g_bufB[(size_t)N_TOT * CH * 42 * 42];
__device__ float  g_feat[(size_t)N_TOT * 1600];
__device__ double g_sums[1024];       // 4 layers x [sum(128) | sumsq(128)]
__device__ float  g_coefA[128];
__device__ float  g_coefB[128];
__device__ double g_volA[40];

#define OFF_PMAX ((size_t)0)
#define OFF_PMIN ((size_t)40000000)

// ---------------- f32x2 helpers ---------------------------------------------
__device__ __forceinline__ unsigned long long pk2(float lo, float hi) {
    unsigned long long r;
    asm("mov.b64 %0, {%1, %2};" : "=l"(r)
        : "r"(__float_as_uint(lo)), "r"(__float_as_uint(hi)));
    return r;
}
__device__ __forceinline__ void upk2(unsigned long long p, float& lo, float& hi) {
    unsigned a, b;
    asm("mov.b64 {%0, %1}, %2;" : "=r"(a), "=r"(b) : "l"(p));
    lo = __uint_as_float(a); hi = __uint_as_float(b);
}
__device__ __forceinline__ void fma2(unsigned long long& acc,
                                     unsigned long long w,
                                     unsigned long long v) {
    asm("fma.rn.f32x2 %0, %1, %2, %0;" : "+l"(acc) : "l"(w), "l"(v));
}

// ---------------- fused conv3x3 + ReLU + stats + minmax-pool ----------------
// Thread: 2x2 output pixels x 8 couts (4 f32x2 channel-pairs).
// Input packs built ONCE per ci; weight pairs loaded via 128-bit LDS.
template<int CIN, int H, int TY, int TX, int TPB, int MINB>
__global__ void __launch_bounds__(TPB, MINB)
conv_fused(const float* __restrict__ in1,     // images [0, split)
           const float* __restrict__ in2,     // images [split, N_TOT)
           int split,
           const float* __restrict__ w,
           const float* __restrict__ bias,
           float* __restrict__ pmax,
           float* __restrict__ pmin,
           double* __restrict__ sums)
{
    constexpr int NPIX = H * H;
    constexpr int HO = H / 2;
    constexpr int NACT = TY * TX;
    constexpr int KT = CIN * 9;
    constexpr int NW = TPB / 32;

    __shared__ __align__(16) float ws[KT * 8];   // [kt][co] co contiguous (8)
    __shared__ float sred[NW][16];

    const int tid = threadIdx.x;
    const int cog = blockIdx.y;
    const int img = blockIdx.z;

    for (int i = tid; i < KT * 8; i += TPB) {
        int co = i / KT, kt = i - co * KT;
        ws[kt * 8 + co] = w[(size_t)(cog * 8 + co) * KT + kt];
    }
    __syncthreads();

    const int ty = tid / TX, tx = tid % TX;
    const int py0 = blockIdx.x * TY + ty;
    const int gy0 = 2 * py0;
    const int gx0 = 2 * tx;
    const bool active = (tid < NACT) && (gy0 < H);

    bool rv[4], cv[4];
#pragma unroll
    for (int r = 0; r < 4; r++) { int yy = gy0 - 1 + r; rv[r] = active && yy >= 0 && yy < H; }
#pragma unroll
    for (int c = 0; c < 4; c++) { int xx = gx0 - 1 + c; cv[c] = active && xx >= 0 && xx < H; }

    const float* base = (img < split) ? (in1 + (size_t)img * CIN * NPIX)
                                      : (in2 + (size_t)(img - split) * CIN * NPIX);
    const float* inp = base + (long)(gy0 - 1) * H + (gx0 - 1);

    unsigned long long acc[4][4];
#pragma unroll
    for (int cp = 0; cp < 4; cp++) {
        unsigned long long bp = pk2(bias[cog * 8 + 2 * cp], bias[cog * 8 + 2 * cp + 1]);
#pragma unroll
        for (int px = 0; px < 4; px++) acc[cp][px] = bp;
    }

    for (int ci = 0; ci < CIN; ci++) {
        const float* ic = inp + (size_t)ci * NPIX;
        unsigned long long ivp[4][4];
#pragma unroll
        for (int r = 0; r < 4; r++)
#pragma unroll
            for (int c = 0; c < 4; c++) {
                float f = (rv[r] && cv[c]) ? __ldg(ic + r * H + c) : 0.f;
                ivp[r][c] = pk2(f, f);
            }

        const float* wk = ws + ci * 72;
#pragma unroll
        for (int ky = 0; ky < 3; ky++)
#pragma unroll
        for (int kx = 0; kx < 3; kx++) {
            const ulonglong2* wp = (const ulonglong2*)(wk + (ky * 3 + kx) * 8);
            ulonglong2 w01 = wp[0];
            ulonglong2 w23 = wp[1];
#pragma unroll
            for (int py = 0; py < 2; py++)
#pragma unroll
            for (int pxx = 0; pxx < 2; pxx++) {
                unsigned long long v = ivp[py + ky][pxx + kx];
                int px = py * 2 + pxx;
                fma2(acc[0][px], w01.x, v);
                fma2(acc[1][px], w01.y, v);
                fma2(acc[2][px], w23.x, v);
                fma2(acc[3][px], w23.y, v);
            }
        }
    }

    bool pv[4];
#pragma unroll
    for (int py = 0; py < 2; py++)
#pragma unroll
        for (int pxx = 0; pxx < 2; pxx++)
            pv[py * 2 + pxx] = active && (gy0 + py) < H && (gx0 + pxx) < H;

    const bool wr = active && py0 < HO && tx < HO;
    const int grp = (img >= N_SUP);
    const int wid = tid >> 5, lid = tid & 31;

    float* pmax_b = pmax + ((size_t)img * CH + cog * 8) * (HO * HO) + py0 * HO + tx;
    float* pmin_b = pmin + ((size_t)img * CH + cog * 8) * (HO * HO) + py0 * HO + tx;

#pragma unroll
    for (int cp = 0; cp < 4; cp++) {
#pragma unroll
        for (int j = 0; j < 2; j++) {
            float r0, r1, r2, r3, t;
            upk2(acc[cp][0], r0, t); if (j) r0 = t;
            upk2(acc[cp][1], r1, t); if (j) r1 = t;
            upk2(acc[cp][2], r2, t); if (j) r2 = t;
            upk2(acc[cp][3], r3, t); if (j) r3 = t;
            r0 = fmaxf(r0, 0.f); r1 = fmaxf(r1, 0.f);
            r2 = fmaxf(r2, 0.f); r3 = fmaxf(r3, 0.f);

            float s0 = pv[0] ? r0 : 0.f, s1 = pv[1] ? r1 : 0.f;
            float s2 = pv[2] ? r2 : 0.f, s3 = pv[3] ? r3 : 0.f;
            float s = s0 + s1 + s2 + s3;
            float q = s0 * s0 + s1 * s1 + s2 * s2 + s3 * s3;
#pragma unroll
            for (int o = 16; o; o >>= 1) {
                s += __shfl_xor_sync(0xffffffffu, s, o);
                q += __shfl_xor_sync(0xffffffffu, q, o);
            }
            int co = cp * 2 + j;
            if (lid == 0) { sred[wid][co] = s; sred[wid][co + 8] = q; }

            if (wr) {
                float mx = fmaxf(fmaxf(r0, r1), fmaxf(r2, r3));
                float mn = fminf(fminf(r0, r1), fminf(r2, r3));
                pmax_b[(size_t)co * HO * HO] = mx;
                pmin_b[(size_t)co * HO * HO] = mn;
            }
        }
    }
    __syncthreads();

    if (tid < 16) {
        int co = tid & 7, isq = tid >> 3;
        float acc2 = 0.f;
#pragma unroll
        for (int ww = 0; ww < NW; ww++) acc2 += sred[ww][co + isq * 8];
        atomicAdd(&sums[isq * 128 + grp * 64 + cog * 8 + co], (double)acc2);
    }
}

// ---------------- zero all 4 layers' sums ------------------------------------
__global__ void zero_all(double* __restrict__ sums)
{
    int i = blockIdx.x * blockDim.x + threadIdx.x;
    if (i < 1024) sums[i] = 0.0;
}

__global__ void bn_finalize(const double* __restrict__ sums,
                            const float* __restrict__ g,
                            const float* __restrict__ be,
                            int NPIX,
                            float* __restrict__ coefA,
                            float* __restrict__ coefB)
{
    int i = threadIdx.x;
    if (i >= 128) return;
    int grp = i / 64, c = i % 64;
    double cnt = (double)(grp ? N_SMP : N_SUP) * NPIX;
    double mean = sums[i] / cnt;
    double var  = sums[128 + i] / cnt - mean * mean;
    double a = (double)g[c] * rsqrt(var + EPSBN);
    coefA[i] = (float)a;
    coefB[i] = (float)((double)be[c] - mean * a);
}

// ---------------- pick pooled value and apply affine BN ---------------------
__global__ void bn_apply(const float* __restrict__ pmax,
                         const float* __restrict__ pmin,
                         const float* __restrict__ coefA,
                         const float* __restrict__ coefB,
                         float* __restrict__ out,
                         int plane, long total)
{
    long idx = (long)blockIdx.x * blockDim.x + threadIdx.x;
    if (idx >= total) return;
    int c = (int)((idx / plane) % CH);
    int n = (int)(idx / ((long)plane * CH));
    int grp = (n >= N_SUP);
    float a = coefA[grp * 64 + c], b = coefB[grp * 64 + c];
    float m = (a > 0.f) ? pmax[idx] : pmin[idx];
    out[idx] = fmaf(m, a, b);
}

// ---------------- simplex volumes -------------------------------------------
__device__ __forceinline__ double det_elim(double* G, int n)
{
    double det = 1.0;
    for (int k = 0; k < n; k++) {
        double piv = G[k * n + k];
        det *= piv;
        double inv = 1.0 / piv;
        for (int i = k + 1; i < n; i++) {
            double f = G[i * n + k] * inv;
            for (int j = k + 1; j < n; j++) G[i * n + j] -= f * G[k * n + j];
        }
    }
    return det;
}

__global__ void volA_kernel(const float* __restrict__ feat, double* __restrict__ volA)
{
    int bw = blockIdx.x;
    int b = bw / 5, w = bw % 5;
    const float* base = feat + ((size_t)(b * 25 + w * 5)) * 1600;

    double acc[10];
#pragma unroll
    for (int k = 0; k < 10; k++) acc[k] = 0.0;

    for (int d = threadIdx.x; d < 1600; d += blockDim.x) {
        float s0 = base[d];
        float a[4];
        a[0] = base[1600 + d] - s0;
        a[1] = base[3200 + d] - s0;
        a[2] = base[4800 + d] - s0;
        a[3] = base[6400 + d] - s0;
        int k = 0;
#pragma unroll
        for (int i = 0; i < 4; i++)
#pragma unroll
            for (int j = i; j < 4; j++)
                acc[k++] += (double)a[i] * a[j];
    }
    __shared__ double sh[128];
    __shared__ double Gp[10];
    int tid = threadIdx.x;
    for (int k = 0; k < 10; k++) {
        sh[tid] = acc[k]; __syncthreads();
        for (int r = 64; r > 0; r >>= 1) { if (tid < r) sh[tid] += sh[tid + r]; __syncthreads(); }
        if (tid == 0) Gp[k] = sh[0];
        __syncthreads();
    }
    if (tid == 0) {
        double G[16];
        int k = 0;
        for (int i = 0; i < 4; i++)
            for (int j = i; j < 4; j++) { G[i * 4 + j] = Gp[k]; G[j * 4 + i] = Gp[k]; k++; }
        volA[bw] = det_elim(G, 4);
    }
}

__global__ void volB_kernel(const float* __restrict__ feat,
                            const double* __restrict__ volA,
                            float* __restrict__ out)
{
    int bx = blockIdx.x;
    int w = bx % 5;
    int q = (bx / 5) % 15;
    int b = bx / 75;
    const float* sm = feat + ((size_t)(N_SUP + b * 15 + q)) * 1600;
    const float* s0 = feat + ((size_t)(b * 25 + w * 5)) * 1600;

    double acc[15];
#pragma unroll
    for (int k = 0; k < 15; k++) acc[k] = 0.0;

    for (int d = threadIdx.x; d < 1600; d += blockDim.x) {
        float sv = sm[d];
        float r[5];
#pragma unroll
        for (int s = 0; s < 5; s++) r[s] = s0[(size_t)s * 1600 + d] - sv;
        int k = 0;
#pragma unroll
        for (int i = 0; i < 5; i++)
#pragma unroll
            for (int j = i; j < 5; j++)
                acc[k++] += (double)r[i] * r[j];
    }
    __shared__ double sh[128];
    __shared__ double Gp[15];
    int tid = threadIdx.x;
    for (int k = 0; k < 15; k++) {
        sh[tid] = acc[k]; __syncthreads();
        for (int r = 64; r > 0; r >>= 1) { if (tid < r) sh[tid] += sh[tid + r]; __syncthreads(); }
        if (tid == 0) Gp[k] = sh[0];
        __syncthreads();
    }
    if (tid == 0) {
        double G[25];
        int k = 0;
        for (int i = 0; i < 5; i++)
            for (int j = i; j < 5; j++) { G[i * 5 + j] = Gp[k]; G[j * 5 + i] = Gp[k]; k++; }
        double detB = det_elim(G, 5);
        out[bx] = (float)(-(detB / volA[b * 5 + w]));
    }
}

// ---------------- host orchestration ----------------------------------------
extern "C" void kernel_launch(void* const* d_in, const int* in_sizes, int n_in,
                              void* d_out, int out_size)
{
    const float* sup = (const float*)d_in[0];
    const float* smp = (const float*)d_in[2];
    const float* W[4]  = {(const float*)d_in[3],  (const float*)d_in[7],
                          (const float*)d_in[11], (const float*)d_in[15]};
    const float* Bb[4] = {(const float*)d_in[4],  (const float*)d_in[8],
                          (const float*)d_in[12], (const float*)d_in[16]};
    const float* Gg[4] = {(const float*)d_in[5],  (const float*)d_in[9],
                          (const float*)d_in[13], (const float*)d_in[17]};
    const float* Be[4] = {(const float*)d_in[6],  (const float*)d_in[10],
                          (const float*)d_in[14], (const float*)d_in[18]};
    float* out = (float*)d_out;

    float  *bufA, *bufB, *feat, *coefA, *coefB;
    double *sums, *volA;
    cudaGetSymbolAddress((void**)&bufA,  g_bufA);
    cudaGetSymbolAddress((void**)&bufB,  g_bufB);
    cudaGetSymbolAddress((void**)&feat,  g_feat);
    cudaGetSymbolAddress((void**)&sums,  g_sums);
    cudaGetSymbolAddress((void**)&coefA, g_coefA);
    cudaGetSymbolAddress((void**)&coefB, g_coefB);
    cudaGetSymbolAddress((void**)&volA,  g_volA);

    float* pmax = bufA + OFF_PMAX;
    float* pmin = bufA + OFF_PMIN;

    zero_all<<<4, 256>>>(sums);

    // ---- layer 1: 3 -> 64, 84x84 -> pooled 42x42 (reads sup/smp directly) ----
    conv_fused<3, 84, 6, 42, 256, 2><<<dim3(7, 8, N_TOT), 256>>>(
        sup, smp, N_SUP, W[0], Bb[0], pmax, pmin, sums + 0);
    bn_finalize<<<1, 128>>>(sums + 0, Gg[0], Be[0], 84 * 84, coefA, coefB);
    {
        long total = (long)N_TOT * CH * 42 * 42;
        bn_apply<<<(unsigned)((total + 255) / 256), 256>>>(pmax, pmin, coefA, coefB, bufB, 42 * 42, total);
    }

    // ---- layer 2: 64 -> 64, 42x42 -> pooled 21x21 ----
    conv_fused<64, 42, 21, 21, 448, 1><<<dim3(1, 8, N_TOT), 448>>>(
        bufB, bufB, N_TOT, W[1], Bb[1], pmax, pmin, sums + 256);
    bn_finalize<<<1, 128>>>(sums + 256, Gg[1], Be[1], 42 * 42, coefA, coefB);
    {
        long total = (long)N_TOT * CH * 21 * 21;
        bn_apply<<<(unsigned)((total + 255) / 256), 256>>>(pmax, pmin, coefA, coefB, bufB, 21 * 21, total);
    }

    // ---- layer 3: 64 -> 64, 21x21 -> pooled 10x10 ----
    conv_fused<64, 21, 11, 11, 128, 4><<<dim3(1, 8, N_TOT), 128>>>(
        bufB, bufB, N_TOT, W[2], Bb[2], pmax, pmin, sums + 512);
    bn_finalize<<<1, 128>>>(sums + 512, Gg[2], Be[2], 21 * 21, coefA, coefB);
    {
        long total = (long)N_TOT * CH * 10 * 10;
        bn_apply<<<(unsigned)((total + 255) / 256), 256>>>(pmax, pmin, coefA, coefB, bufB, 10 * 10, total);
    }

    // ---- layer 4: 64 -> 64, 10x10 -> pooled 5x5 (features) ----
    conv_fused<64, 10, 5, 5, 32, 16><<<dim3(1, 8, N_TOT), 32>>>(
        bufB, bufB, N_TOT, W[3], Bb[3], pmax, pmin, sums + 768);
    bn_finalize<<<1, 128>>>(sums + 768, Gg[3], Be[3], 10 * 10, coefA, coefB);
    {
        long total = (long)N_TOT * CH * 5 * 5;
        bn_apply<<<(unsigned)((total + 255) / 256), 256>>>(pmax, pmin, coefA, coefB, feat, 5 * 5, total);
    }

    // ---- simplex similarities ----
    volA_kernel<<<40, 128>>>(feat, volA);
    volB_kernel<<<600, 128>>>(feat, volA, out);
}

// round 8
// speedup vs baseline: 2.5303x; 1.0097x over previous
#include <cuda_runtime.h>
#include <cstddef>

#define N_SUP 200
#define N_SMP 120
#define N_TOT 320
#define CH 64
#define EPSBN 1e-5

// ---------------- scratch (device globals; no allocation allowed) ----------
__device__ float  g_bufA[(size_t)N_TOT * CH * 84 * 84];   // carved into pmax/pmin
__device__ float  g_bufB[(size_t)N_TOT * CH * 42 * 42];
__device__ float  g_feat[(size_t)N_TOT * 1600];
__device__ double g_sums[1024];       // 4 layers x [sum(128) | sumsq(128)]
__device__ float  g_coefA[128];
__device__ float  g_coefB[128];
__device__ double g_volA[40];

#define OFF_PMAX ((size_t)0)
#define OFF_PMIN ((size_t)40000000)

// ---------------- f32x2 helpers ---------------------------------------------
__device__ __forceinline__ unsigned long long pk2(float lo, float hi) {
    unsigned long long r;
    asm("mov.b64 %0, {%1, %2};" : "=l"(r)
        : "r"(__float_as_uint(lo)), "r"(__float_as_uint(hi)));
    return r;
}
__device__ __forceinline__ void upk2(unsigned long long p, float& lo, float& hi) {
    unsigned a, b;
    asm("mov.b64 {%0, %1}, %2;" : "=r"(a), "=r"(b) : "l"(p));
    lo = __uint_as_float(a); hi = __uint_as_float(b);
}
__device__ __forceinline__ void fma2(unsigned long long& acc,
                                     unsigned long long w,
                                     unsigned long long v) {
    asm("fma.rn.f32x2 %0, %1, %2, %0;" : "+l"(acc) : "l"(w), "l"(v));
}

// ---------------- fused conv3x3 + ReLU + stats + minmax-pool ----------------
// Thread: 2x2 output pixels x 8 couts (4 f32x2 channel-pairs).
// Epilogue: smem transpose reduction (no per-channel shfl trees).
template<int CIN, int H, int TY, int TX, int TPB, int MINB>
__global__ void __launch_bounds__(TPB, MINB)
conv_fused(const float* __restrict__ in1,     // images [0, split)
           const float* __restrict__ in2,     // images [split, N_TOT)
           int split,
           const float* __restrict__ w,
           const float* __restrict__ bias,
           float* __restrict__ pmax,
           float* __restrict__ pmin,
           double* __restrict__ sums)
{
    constexpr int NPIX = H * H;
    constexpr int HO = H / 2;
    constexpr int NACT = TY * TX;
    constexpr int KT = CIN * 9;
    constexpr int NW = TPB / 32;

    __shared__ __align__(16) float ws[KT * 8];   // [kt][co] co contiguous (8)
    __shared__ float sred[16][TPB];              // rows 0..7 = sum, 8..15 = sumsq

    const int tid = threadIdx.x;
    const int cog = blockIdx.y;
    const int img = blockIdx.z;

    for (int i = tid; i < KT * 8; i += TPB) {
        int co = i / KT, kt = i - co * KT;
        ws[kt * 8 + co] = w[(size_t)(cog * 8 + co) * KT + kt];
    }
    __syncthreads();

    const int ty = tid / TX, tx = tid % TX;
    const int py0 = blockIdx.x * TY + ty;
    const int gy0 = 2 * py0;
    const int gx0 = 2 * tx;
    const bool active = (tid < NACT) && (gy0 < H);

    bool rv[4], cv[4];
#pragma unroll
    for (int r = 0; r < 4; r++) { int yy = gy0 - 1 + r; rv[r] = active && yy >= 0 && yy < H; }
#pragma unroll
    for (int c = 0; c < 4; c++) { int xx = gx0 - 1 + c; cv[c] = active && xx >= 0 && xx < H; }

    const float* base = (img < split) ? (in1 + (size_t)img * CIN * NPIX)
                                      : (in2 + (size_t)(img - split) * CIN * NPIX);
    const float* inp = base + (long)(gy0 - 1) * H + (gx0 - 1);

    unsigned long long acc[4][4];
#pragma unroll
    for (int cp = 0; cp < 4; cp++) {
        unsigned long long bp = pk2(bias[cog * 8 + 2 * cp], bias[cog * 8 + 2 * cp + 1]);
#pragma unroll
        for (int px = 0; px < 4; px++) acc[cp][px] = bp;
    }

    for (int ci = 0; ci < CIN; ci++) {
        const float* ic = inp + (size_t)ci * NPIX;
        unsigned long long ivp[4][4];
#pragma unroll
        for (int r = 0; r < 4; r++)
#pragma unroll
            for (int c = 0; c < 4; c++) {
                float f = (rv[r] && cv[c]) ? __ldg(ic + r * H + c) : 0.f;
                ivp[r][c] = pk2(f, f);
            }

        const float* wk = ws + ci * 72;
#pragma unroll
        for (int ky = 0; ky < 3; ky++)
#pragma unroll
        for (int kx = 0; kx < 3; kx++) {
            const ulonglong2* wp = (const ulonglong2*)(wk + (ky * 3 + kx) * 8);
            ulonglong2 w01 = wp[0];
            ulonglong2 w23 = wp[1];
#pragma unroll
            for (int py = 0; py < 2; py++)
#pragma unroll
            for (int pxx = 0; pxx < 2; pxx++) {
                unsigned long long v = ivp[py + ky][pxx + kx];
                int px = py * 2 + pxx;
                fma2(acc[0][px], w01.x, v);
                fma2(acc[1][px], w01.y, v);
                fma2(acc[2][px], w23.x, v);
                fma2(acc[3][px], w23.y, v);
            }
        }
    }

    bool pv[4];
#pragma unroll
    for (int py = 0; py < 2; py++)
#pragma unroll
        for (int pxx = 0; pxx < 2; pxx++)
            pv[py * 2 + pxx] = active && (gy0 + py) < H && (gx0 + pxx) < H;

    const bool wr = active && py0 < HO && tx < HO;
    const int grp = (img >= N_SUP);
    const int wid = tid >> 5, lid = tid & 31;

    float* pmax_b = pmax + ((size_t)img * CH + cog * 8) * (HO * HO) + py0 * HO + tx;
    float* pmin_b = pmin + ((size_t)img * CH + cog * 8) * (HO * HO) + py0 * HO + tx;

#pragma unroll
    for (int cp = 0; cp < 4; cp++) {
#pragma unroll
        for (int j = 0; j < 2; j++) {
            float r0, r1, r2, r3, t;
            upk2(acc[cp][0], r0, t); if (j) r0 = t;
            upk2(acc[cp][1], r1, t); if (j) r1 = t;
            upk2(acc[cp][2], r2, t); if (j) r2 = t;
            upk2(acc[cp][3], r3, t); if (j) r3 = t;
            r0 = fmaxf(r0, 0.f); r1 = fmaxf(r1, 0.f);
            r2 = fmaxf(r2, 0.f); r3 = fmaxf(r3, 0.f);

            float s0 = pv[0] ? r0 : 0.f, s1 = pv[1] ? r1 : 0.f;
            float s2 = pv[2] ? r2 : 0.f, s3 = pv[3] ? r3 : 0.f;
            int co = cp * 2 + j;
            sred[co][tid]     = s0 + s1 + s2 + s3;
            sred[co + 8][tid] = s0 * s0 + s1 * s1 + s2 * s2 + s3 * s3;

            if (wr) {
                float mx = fmaxf(fmaxf(r0, r1), fmaxf(r2, r3));
                float mn = fminf(fminf(r0, r1), fminf(r2, r3));
                pmax_b[(size_t)co * HO * HO] = mx;
                pmin_b[(size_t)co * HO * HO] = mn;
            }
        }
    }
    __syncthreads();

    // each warp reduces whole rows (columns of sred) — 1 butterfly per row
    for (int row = wid; row < 16; row += NW) {
        float v = 0.f;
        for (int i = lid; i < TPB; i += 32) v += sred[row][i];
#pragma unroll
        for (int o = 16; o; o >>= 1) v += __shfl_xor_sync(0xffffffffu, v, o);
        if (lid == 0) {
            int co = row & 7, isq = row >> 3;
            atomicAdd(&sums[isq * 128 + grp * 64 + cog * 8 + co], (double)v);
        }
    }
}

// ---------------- zero all 4 layers' sums ------------------------------------
__global__ void zero_all(double* __restrict__ sums)
{
    int i = blockIdx.x * blockDim.x + threadIdx.x;
    if (i < 1024) sums[i] = 0.0;
}

// dummy/profiling-alignment launch: also zeroes volA (harmless; rewritten later)
__global__ void zero_vol(double* __restrict__ v)
{
    if (threadIdx.x < 40) v[threadIdx.x] = 0.0;
}

__global__ void bn_finalize(const double* __restrict__ sums,
                            const float* __restrict__ g,
                            const float* __restrict__ be,
                            int NPIX,
                            float* __restrict__ coefA,
                            float* __restrict__ coefB)
{
    int i = threadIdx.x;
    if (i >= 128) return;
    int grp = i / 64, c = i % 64;
    double cnt = (double)(grp ? N_SMP : N_SUP) * NPIX;
    double mean = sums[i] / cnt;
    double var  = sums[128 + i] / cnt - mean * mean;
    double a = (double)g[c] * rsqrt(var + EPSBN);
    coefA[i] = (float)a;
    coefB[i] = (float)((double)be[c] - mean * a);
}

// ---------------- pick pooled value and apply affine BN ---------------------
// grid: (plane chunks, channel, image) -> zero integer division
__global__ void bn_apply(const float* __restrict__ pmax,
                         const float* __restrict__ pmin,
                         const float* __restrict__ coefA,
                         const float* __restrict__ coefB,
                         float* __restrict__ out,
                         int plane)
{
    int i = blockIdx.x * blockDim.x + threadIdx.x;
    if (i >= plane) return;
    int c = blockIdx.y;
    int n = blockIdx.z;
    int grp = (n >= N_SUP);
    float a = coefA[grp * 64 + c], b = coefB[grp * 64 + c];
    size_t off = ((size_t)n * CH + c) * plane + i;
    const float* p = (a > 0.f) ? pmax : pmin;
    out[off] = fmaf(p[off], a, b);
}

// ---------------- simplex volumes -------------------------------------------
__device__ __forceinline__ double det_elim(double* G, int n)
{
    double det = 1.0;
    for (int k = 0; k < n; k++) {
        double piv = G[k * n + k];
        det *= piv;
        double inv = 1.0 / piv;
        for (int i = k + 1; i < n; i++) {
            double f = G[i * n + k] * inv;
            for (int j = k + 1; j < n; j++) G[i * n + j] -= f * G[k * n + j];
        }
    }
    return det;
}

__global__ void volA_kernel(const float* __restrict__ feat, double* __restrict__ volA)
{
    int bw = blockIdx.x;
    int b = bw / 5, w = bw % 5;
    const float* base = feat + ((size_t)(b * 25 + w * 5)) * 1600;

    double acc[10];
#pragma unroll
    for (int k = 0; k < 10; k++) acc[k] = 0.0;

    for (int d = threadIdx.x; d < 1600; d += blockDim.x) {
        float s0 = base[d];
        float a[4];
        a[0] = base[1600 + d] - s0;
        a[1] = base[3200 + d] - s0;
        a[2] = base[4800 + d] - s0;
        a[3] = base[6400 + d] - s0;
        int k = 0;
#pragma unroll
        for (int i = 0; i < 4; i++)
#pragma unroll
            for (int j = i; j < 4; j++)
                acc[k++] += (double)a[i] * a[j];
    }
    __shared__ double sh[128];
    __shared__ double Gp[10];
    int tid = threadIdx.x;
    for (int k = 0; k < 10; k++) {
        sh[tid] = acc[k]; __syncthreads();
        for (int r = 64; r > 0; r >>= 1) { if (tid < r) sh[tid] += sh[tid + r]; __syncthreads(); }
        if (tid == 0) Gp[k] = sh[0];
        __syncthreads();
    }
    if (tid == 0) {
        double G[16];
        int k = 0;
        for (int i = 0; i < 4; i++)
            for (int j = i; j < 4; j++) { G[i * 4 + j] = Gp[k]; G[j * 4 + i] = Gp[k]; k++; }
        volA[bw] = det_elim(G, 4);
    }
}

__global__ void volB_kernel(const float* __restrict__ feat,
                            const double* __restrict__ volA,
                            float* __restrict__ out)
{
    int bx = blockIdx.x;
    int w = bx % 5;
    int q = (bx / 5) % 15;
    int b = bx / 75;
    const float* sm = feat + ((size_t)(N_SUP + b * 15 + q)) * 1600;
    const float* s0 = feat + ((size_t)(b * 25 + w * 5)) * 1600;

    double acc[15];
#pragma unroll
    for (int k = 0; k < 15; k++) acc[k] = 0.0;

    for (int d = threadIdx.x; d < 1600; d += blockDim.x) {
        float sv = sm[d];
        float r[5];
#pragma unroll
        for (int s = 0; s < 5; s++) r[s] = s0[(size_t)s * 1600 + d] - sv;
        int k = 0;
#pragma unroll
        for (int i = 0; i < 5; i++)
#pragma unroll
            for (int j = i; j < 5; j++)
                acc[k++] += (double)r[i] * r[j];
    }
    __shared__ double sh[128];
    __shared__ double Gp[15];
    int tid = threadIdx.x;
    for (int k = 0; k < 15; k++) {
        sh[tid] = acc[k]; __syncthreads();
        for (int r = 64; r > 0; r >>= 1) { if (tid < r) sh[tid] += sh[tid + r]; __syncthreads(); }
        if (tid == 0) Gp[k] = sh[0];
        __syncthreads();
    }
    if (tid == 0) {
        double G[25];
        int k = 0;
        for (int i = 0; i < 5; i++)
            for (int j = i; j < 5; j++) { G[i * 5 + j] = Gp[k]; G[j * 5 + i] = Gp[k]; k++; }
        double detB = det_elim(G, 5);
        out[bx] = (float)(-(detB / volA[b * 5 + w]));
    }
}

// ---------------- host orchestration ----------------------------------------
extern "C" void kernel_launch(void* const* d_in, const int* in_sizes, int n_in,
                              void* d_out, int out_size)
{
    const float* sup = (const float*)d_in[0];
    const float* smp = (const float*)d_in[2];
    const float* W[4]  = {(const float*)d_in[3],  (const float*)d_in[7],
                          (const float*)d_in[11], (const float*)d_in[15]};
    const float* Bb[4] = {(const float*)d_in[4],  (const float*)d_in[8],
                          (const float*)d_in[12], (const float*)d_in[16]};
    const float* Gg[4] = {(const float*)d_in[5],  (const float*)d_in[9],
                          (const float*)d_in[13], (const float*)d_in[17]};
    const float* Be[4] = {(const float*)d_in[6],  (const float*)d_in[10],
                          (const float*)d_in[14], (const float*)d_in[18]};
    float* out = (float*)d_out;

    float  *bufA, *bufB, *feat, *coefA, *coefB;
    double *sums, *volA;
    cudaGetSymbolAddress((void**)&bufA,  g_bufA);
    cudaGetSymbolAddress((void**)&bufB,  g_bufB);
    cudaGetSymbolAddress((void**)&feat,  g_feat);
    cudaGetSymbolAddress((void**)&sums,  g_sums);
    cudaGetSymbolAddress((void**)&coefA, g_coefA);
    cudaGetSymbolAddress((void**)&coefB, g_coefB);
    cudaGetSymbolAddress((void**)&volA,  g_volA);

    float* pmax = bufA + OFF_PMAX;
    float* pmin = bufA + OFF_PMIN;

    // launch #1
    zero_all<<<4, 256>>>(sums);

    // ---- layer 1: 3 -> 64, 84x84 -> pooled 42x42 ----  (#2,#3,#4)
    conv_fused<3, 84, 6, 42, 256, 2><<<dim3(7, 8, N_TOT), 256>>>(
        sup, smp, N_SUP, W[0], Bb[0], pmax, pmin, sums + 0);
    bn_finalize<<<1, 128>>>(sums + 0, Gg[0], Be[0], 84 * 84, coefA, coefB);
    bn_apply<<<dim3(7, 64, N_TOT), 256>>>(pmax, pmin, coefA, coefB, bufB, 42 * 42);

    // launch #5 (alignment dummy: puts conv2 at ncu's skip-5 capture slot)
    zero_vol<<<1, 64>>>(volA);

    // ---- layer 2: 64 -> 64, 42x42 -> pooled 21x21 ----  (#6,#7,#8)
    conv_fused<64, 42, 21, 21, 448, 1><<<dim3(1, 8, N_TOT), 448>>>(
        bufB, bufB, N_TOT, W[1], Bb[1], pmax, pmin, sums + 256);
    bn_finalize<<<1, 128>>>(sums + 256, Gg[1], Be[1], 42 * 42, coefA, coefB);
    bn_apply<<<dim3(2, 64, N_TOT), 256>>>(pmax, pmin, coefA, coefB, bufB, 21 * 21);

    // ---- layer 3: 64 -> 64, 21x21 -> pooled 10x10 ----
    conv_fused<64, 21, 11, 11, 128, 4><<<dim3(1, 8, N_TOT), 128>>>(
        bufB, bufB, N_TOT, W[2], Bb[2], pmax, pmin, sums + 512);
    bn_finalize<<<1, 128>>>(sums + 512, Gg[2], Be[2], 21 * 21, coefA, coefB);
    bn_apply<<<dim3(1, 64, N_TOT), 128>>>(pmax, pmin, coefA, coefB, bufB, 10 * 10);

    // ---- layer 4: 64 -> 64, 10x10 -> pooled 5x5 (features) ----
    conv_fused<64, 10, 5, 5, 32, 16><<<dim3(1, 8, N_TOT), 32>>>(
        bufB, bufB, N_TOT, W[3], Bb[3], pmax, pmin, sums + 768);
    bn_finalize<<<1, 128>>>(sums + 768, Gg[3], Be[3], 10 * 10, coefA, coefB);
    bn_apply<<<dim3(1, 64, N_TOT), 32>>>(pmax, pmin, coefA, coefB, feat, 5 * 5);

    // ---- simplex similarities ----
    volA_kernel<<<40, 128>>>(feat, volA);
    volB_kernel<<<600, 128>>>(feat, volA, out);
}

// round 10
// speedup vs baseline: 2.8352x; 1.1205x over previous
#include <cuda_runtime.h>
#include <cstddef>

#define N_SUP 200
#define N_SMP 120
#define N_TOT 320
#define CH 64
#define EPSBN 1e-5

// ---------------- scratch (device globals; no allocation allowed) ----------
__device__ float  g_bufA[(size_t)N_TOT * CH * 84 * 84];   // carved into pmax/pmin
__device__ float  g_bufB[(size_t)N_TOT * CH * 42 * 42];
__device__ float  g_feat[(size_t)N_TOT * 1600];
__device__ double g_sums[1024];       // 4 layers x [sum(128) | sumsq(128)], zero-init; re-zeroed by bn_finalize
__device__ float  g_coefA[128];
__device__ float  g_coefB[128];
__device__ double g_volA[40];

#define OFF_PMAX ((size_t)0)
#define OFF_PMIN ((size_t)40000000)

// ---------------- f32x2 helpers ---------------------------------------------
__device__ __forceinline__ unsigned long long pk2(float lo, float hi) {
    unsigned long long r;
    asm("mov.b64 %0, {%1, %2};" : "=l"(r)
        : "r"(__float_as_uint(lo)), "r"(__float_as_uint(hi)));
    return r;
}
__device__ __forceinline__ void upk2(unsigned long long p, float& lo, float& hi) {
    unsigned a, b;
    asm("mov.b64 {%0, %1}, %2;" : "=r"(a), "=r"(b) : "l"(p));
    lo = __uint_as_float(a); hi = __uint_as_float(b);
}
__device__ __forceinline__ void fma2(unsigned long long& acc,
                                     unsigned long long w,
                                     unsigned long long v) {
    asm("fma.rn.f32x2 %0, %1, %2, %0;" : "+l"(acc) : "l"(w), "l"(v));
}

// ---------------- fused conv3x3 + ReLU + stats + minmax-pool ----------------
// Thread: 2x2 output pixels x 8 couts (4 f32x2 channel-pairs).
// ci loop software-pipelined: next channel's 16 inputs prefetched during FMAs.
template<int CIN, int H, int TY, int TX, int TPB, int MINB>
__global__ void __launch_bounds__(TPB, MINB)
conv_fused(const float* __restrict__ in1,     // images [0, split)
           const float* __restrict__ in2,     // images [split, N_TOT)
           int split,
           const float* __restrict__ w,
           const float* __restrict__ bias,
           float* __restrict__ pmax,
           float* __restrict__ pmin,
           double* __restrict__ sums)
{
    constexpr int NPIX = H * H;
    constexpr int HO = H / 2;
    constexpr int NACT = TY * TX;
    constexpr int KT = CIN * 9;
    constexpr int NW = TPB / 32;

    __shared__ __align__(16) float ws[KT * 8];   // [kt][co] co contiguous (8)
    __shared__ float sred[16][TPB];              // rows 0..7 = sum, 8..15 = sumsq

    const int tid = threadIdx.x;
    const int cog = blockIdx.y;
    const int img = blockIdx.z;

    for (int i = tid; i < KT * 8; i += TPB) {
        int co = i / KT, kt = i - co * KT;
        ws[kt * 8 + co] = w[(size_t)(cog * 8 + co) * KT + kt];
    }
    __syncthreads();

    const int ty = tid / TX, tx = tid % TX;
    const int py0 = blockIdx.x * TY + ty;
    const int gy0 = 2 * py0;
    const int gx0 = 2 * tx;
    const bool active = (tid < NACT) && (gy0 < H);

    bool rv[4], cv[4];
#pragma unroll
    for (int r = 0; r < 4; r++) { int yy = gy0 - 1 + r; rv[r] = active && yy >= 0 && yy < H; }
#pragma unroll
    for (int c = 0; c < 4; c++) { int xx = gx0 - 1 + c; cv[c] = active && xx >= 0 && xx < H; }

    const float* base = (img < split) ? (in1 + (size_t)img * CIN * NPIX)
                                      : (in2 + (size_t)(img - split) * CIN * NPIX);
    const float* inp = base + (long)(gy0 - 1) * H + (gx0 - 1);

    unsigned long long acc[4][4];
#pragma unroll
    for (int cp = 0; cp < 4; cp++) {
        unsigned long long bp = pk2(bias[cog * 8 + 2 * cp], bias[cog * 8 + 2 * cp + 1]);
#pragma unroll
        for (int px = 0; px < 4; px++) acc[cp][px] = bp;
    }

    // ---- software-pipelined mainloop ----
    float cur[16];
#pragma unroll
    for (int r = 0; r < 4; r++)
#pragma unroll
        for (int c = 0; c < 4; c++)
            cur[r * 4 + c] = (rv[r] && cv[c]) ? __ldg(inp + r * H + c) : 0.f;

#pragma unroll 2
    for (int ci = 0; ci < CIN; ci++) {
        float nxt[16];
        if (ci + 1 < CIN) {
            const float* icn = inp + (size_t)(ci + 1) * NPIX;
#pragma unroll
            for (int r = 0; r < 4; r++)
#pragma unroll
                for (int c = 0; c < 4; c++)
                    nxt[r * 4 + c] = (rv[r] && cv[c]) ? __ldg(icn + r * H + c) : 0.f;
        }

        unsigned long long ivp[16];
#pragma unroll
        for (int k = 0; k < 16; k++) ivp[k] = pk2(cur[k], cur[k]);

        const float* wk = ws + ci * 72;
#pragma unroll
        for (int ky = 0; ky < 3; ky++)
#pragma unroll
        for (int kx = 0; kx < 3; kx++) {
            const ulonglong2* wp = (const ulonglong2*)(wk + (ky * 3 + kx) * 8);
            ulonglong2 w01 = wp[0];
            ulonglong2 w23 = wp[1];
#pragma unroll
            for (int py = 0; py < 2; py++)
#pragma unroll
            for (int pxx = 0; pxx < 2; pxx++) {
                unsigned long long v = ivp[(py + ky) * 4 + (pxx + kx)];
                int px = py * 2 + pxx;
                fma2(acc[0][px], w01.x, v);
                fma2(acc[1][px], w01.y, v);
                fma2(acc[2][px], w23.x, v);
                fma2(acc[3][px], w23.y, v);
            }
        }

#pragma unroll
        for (int k = 0; k < 16; k++) cur[k] = nxt[k];
    }

    bool pv[4];
#pragma unroll
    for (int py = 0; py < 2; py++)
#pragma unroll
        for (int pxx = 0; pxx < 2; pxx++)
            pv[py * 2 + pxx] = active && (gy0 + py) < H && (gx0 + pxx) < H;

    const bool wr = active && py0 < HO && tx < HO;
    const int grp = (img >= N_SUP);
    const int wid = tid >> 5, lid = tid & 31;

    float* pmax_b = pmax + ((size_t)img * CH + cog * 8) * (HO * HO) + py0 * HO + tx;
    float* pmin_b = pmin + ((size_t)img * CH + cog * 8) * (HO * HO) + py0 * HO + tx;

#pragma unroll
    for (int cp = 0; cp < 4; cp++) {
#pragma unroll
        for (int j = 0; j < 2; j++) {
            float r0, r1, r2, r3, t;
            upk2(acc[cp][0], r0, t); if (j) r0 = t;
            upk2(acc[cp][1], r1, t); if (j) r1 = t;
            upk2(acc[cp][2], r2, t); if (j) r2 = t;
            upk2(acc[cp][3], r3, t); if (j) r3 = t;
            r0 = fmaxf(r0, 0.f); r1 = fmaxf(r1, 0.f);
            r2 = fmaxf(r2, 0.f); r3 = fmaxf(r3, 0.f);

            float s0 = pv[0] ? r0 : 0.f, s1 = pv[1] ? r1 : 0.f;
            float s2 = pv[2] ? r2 : 0.f, s3 = pv[3] ? r3 : 0.f;
            int co = cp * 2 + j;
            sred[co][tid]     = s0 + s1 + s2 + s3;
            sred[co + 8][tid] = s0 * s0 + s1 * s1 + s2 * s2 + s3 * s3;

            if (wr) {
                float mx = fmaxf(fmaxf(r0, r1), fmaxf(r2, r3));
                float mn = fminf(fminf(r0, r1), fminf(r2, r3));
                pmax_b[(size_t)co * HO * HO] = mx;
                pmin_b[(size_t)co * HO * HO] = mn;
            }
        }
    }
    __syncthreads();

    for (int row = wid; row < 16; row += NW) {
        float v = 0.f;
        for (int i = lid; i < TPB; i += 32) v += sred[row][i];
#pragma unroll
        for (int o = 16; o; o >>= 1) v += __shfl_xor_sync(0xffffffffu, v, o);
        if (lid == 0) {
            int co = row & 7, isq = row >> 3;
            atomicAdd(&sums[isq * 128 + grp * 64 + cog * 8 + co], (double)v);
        }
    }
}

// ---------------- BN finalize (reads, then re-zeroes its layer's sums) ------
__global__ void bn_finalize(double* __restrict__ sums,
                            const float* __restrict__ g,
                            const float* __restrict__ be,
                            int NPIX,
                            float* __restrict__ coefA,
                            float* __restrict__ coefB)
{
    int i = threadIdx.x;
    if (i >= 128) return;
    int grp = i / 64, c = i % 64;
    double cnt = (double)(grp ? N_SMP : N_SUP) * NPIX;
    double s  = sums[i];
    double s2 = sums[128 + i];
    sums[i] = 0.0;           // re-arm for next graph replay
    sums[128 + i] = 0.0;
    double mean = s / cnt;
    double var  = s2 / cnt - mean * mean;
    double a = (double)g[c] * rsqrt(var + EPSBN);
    coefA[i] = (float)a;
    coefB[i] = (float)((double)be[c] - mean * a);
}

// ---------------- pick pooled value and apply affine BN (MLP=4) -------------
// grid: (ceil(plane/(TPB*4)), channel, image)
__global__ void bn_apply(const float* __restrict__ pmax,
                         const float* __restrict__ pmin,
                         const float* __restrict__ coefA,
                         const float* __restrict__ coefB,
                         float* __restrict__ out,
                         int plane)
{
    int i0 = (blockIdx.x * blockDim.x) * 4 + threadIdx.x;
    int c = blockIdx.y;
    int n = blockIdx.z;
    int grp = (n >= N_SUP);
    float a = coefA[grp * 64 + c], b = coefB[grp * 64 + c];
    size_t bofs = ((size_t)n * CH + c) * plane;
    const float* p = (a > 0.f) ? pmax : pmin;

    float v[4];
    int idx[4];
#pragma unroll
    for (int k = 0; k < 4; k++) {
        idx[k] = i0 + k * blockDim.x;
        v[k] = (idx[k] < plane) ? p[bofs + idx[k]] : 0.f;
    }
#pragma unroll
    for (int k = 0; k < 4; k++)
        if (idx[k] < plane) out[bofs + idx[k]] = fmaf(v[k], a, b);
}

// ---------------- simplex volumes -------------------------------------------
__device__ __forceinline__ double det_elim(double* G, int n)
{
    double det = 1.0;
    for (int k = 0; k < n; k++) {
        double piv = G[k * n + k];
        det *= piv;
        double inv = 1.0 / piv;
        for (int i = k + 1; i < n; i++) {
            double f = G[i * n + k] * inv;
            for (int j = k + 1; j < n; j++) G[i * n + j] -= f * G[k * n + j];
        }
    }
    return det;
}

__global__ void volA_kernel(const float* __restrict__ feat, double* __restrict__ volA)
{
    int bw = blockIdx.x;
    int b = bw / 5, w = bw % 5;
    const float* base = feat + ((size_t)(b * 25 + w * 5)) * 1600;

    double acc[10];
#pragma unroll
    for (int k = 0; k < 10; k++) acc[k] = 0.0;

    for (int d = threadIdx.x; d < 1600; d += blockDim.x) {
        float s0 = base[d];
        float a[4];
        a[0] = base[1600 + d] - s0;
        a[1] = base[3200 + d] - s0;
        a[2] = base[4800 + d] - s0;
        a[3] = base[6400 + d] - s0;
        int k = 0;
#pragma unroll
        for (int i = 0; i < 4; i++)
#pragma unroll
            for (int j = i; j < 4; j++)
                acc[k++] += (double)a[i] * a[j];
    }
    __shared__ double sh[128];
    __shared__ double Gp[10];
    int tid = threadIdx.x;
    for (int k = 0; k < 10; k++) {
        sh[tid] = acc[k]; __syncthreads();
        for (int r = 64; r > 0; r >>= 1) { if (tid < r) sh[tid] += sh[tid + r]; __syncthreads(); }
        if (tid == 0) Gp[k] = sh[0];
        __syncthreads();
    }
    if (tid == 0) {
        double G[16];
        int k = 0;
        for (int i = 0; i < 4; i++)
            for (int j = i; j < 4; j++) { G[i * 4 + j] = Gp[k]; G[j * 4 + i] = Gp[k]; k++; }
        volA[bw] = det_elim(G, 4);
    }
}

__global__ void volB_kernel(const float* __restrict__ feat,
                            const double* __restrict__ volA,
                            float* __restrict__ out)
{
    int bx = blockIdx.x;
    int w = bx % 5;
    int q = (bx / 5) % 15;
    int b = bx / 75;
    const float* sm = feat + ((size_t)(N_SUP + b * 15 + q)) * 1600;
    const float* s0 = feat + ((size_t)(b * 25 + w * 5)) * 1600;

    double acc[15];
#pragma unroll
    for (int k = 0; k < 15; k++) acc[k] = 0.0;

    for (int d = threadIdx.x; d < 1600; d += blockDim.x) {
        float sv = sm[d];
        float r[5];
#pragma unroll
        for (int s = 0; s < 5; s++) r[s] = s0[(size_t)s * 1600 + d] - sv;
        int k = 0;
#pragma unroll
        for (int i = 0; i < 5; i++)
#pragma unroll
            for (int j = i; j < 5; j++)
                acc[k++] += (double)r[i] * r[j];
    }
    __shared__ double sh[128];
    __shared__ double Gp[15];
    int tid = threadIdx.x;
    for (int k = 0; k < 15; k++) {
        sh[tid] = acc[k]; __syncthreads();
        for (int r = 64; r > 0; r >>= 1) { if (tid < r) sh[tid] += sh[tid + r]; __syncthreads(); }
        if (tid == 0) Gp[k] = sh[0];
        __syncthreads();
    }
    if (tid == 0) {
        double G[25];
        int k = 0;
        for (int i = 0; i < 5; i++)
            for (int j = i; j < 5; j++) { G[i * 5 + j] = Gp[k]; G[j * 5 + i] = Gp[k]; k++; }
        double detB = det_elim(G, 5);
        out[bx] = (float)(-(detB / volA[b * 5 + w]));
    }
}

// ---------------- host orchestration ----------------------------------------
extern "C" void kernel_launch(void* const* d_in, const int* in_sizes, int n_in,
                              void* d_out, int out_size)
{
    const float* sup = (const float*)d_in[0];
    const float* smp = (const float*)d_in[2];
    const float* W[4]  = {(const float*)d_in[3],  (const float*)d_in[7],
                          (const float*)d_in[11], (const float*)d_in[15]};
    const float* Bb[4] = {(const float*)d_in[4],  (const float*)d_in[8],
                          (const float*)d_in[12], (const float*)d_in[16]};
    const float* Gg[4] = {(const float*)d_in[5],  (const float*)d_in[9],
                          (const float*)d_in[13], (const float*)d_in[17]};
    const float* Be[4] = {(const float*)d_in[6],  (const float*)d_in[10],
                          (const float*)d_in[14], (const float*)d_in[18]};
    float* out = (float*)d_out;

    float  *bufA, *bufB, *feat, *coefA, *coefB;
    double *sums, *volA;
    cudaGetSymbolAddress((void**)&bufA,  g_bufA);
    cudaGetSymbolAddress((void**)&bufB,  g_bufB);
    cudaGetSymbolAddress((void**)&feat,  g_feat);
    cudaGetSymbolAddress((void**)&sums,  g_sums);
    cudaGetSymbolAddress((void**)&coefA, g_coefA);
    cudaGetSymbolAddress((void**)&coefB, g_coefB);
    cudaGetSymbolAddress((void**)&volA,  g_volA);

    float* pmax = bufA + OFF_PMAX;
    float* pmin = bufA + OFF_PMIN;

    // ---- layer 1: 3 -> 64, 84x84 -> pooled 42x42 ----  (#1,#2,#3)
    conv_fused<3, 84, 6, 42, 256, 2><<<dim3(7, 8, N_TOT), 256>>>(
        sup, smp, N_SUP, W[0], Bb[0], pmax, pmin, sums + 0);
    bn_finalize<<<1, 128>>>(sums + 0, Gg[0], Be[0], 84 * 84, coefA, coefB);
    bn_apply<<<dim3(2, 64, N_TOT), 256>>>(pmax, pmin, coefA, coefB, bufB, 42 * 42);

    // ---- layer 2: 64 -> 64, 42x42 -> pooled 21x21 ----  (#4 = ncu capture slot)
    conv_fused<64, 42, 21, 21, 448, 1><<<dim3(1, 8, N_TOT), 448>>>(
        bufB, bufB, N_TOT, W[1], Bb[1], pmax, pmin, sums + 256);
    bn_finalize<<<1, 128>>>(sums + 256, Gg[1], Be[1], 42 * 42, coefA, coefB);
    bn_apply<<<dim3(1, 64, N_TOT), 128>>>(pmax, pmin, coefA, coefB, bufB, 21 * 21);

    // ---- layer 3: 64 -> 64, 21x21 -> pooled 10x10 ----
    conv_fused<64, 21, 11, 11, 128, 4><<<dim3(1, 8, N_TOT), 128>>>(
        bufB, bufB, N_TOT, W[2], Bb[2], pmax, pmin, sums + 512);
    bn_finalize<<<1, 128>>>(sums + 512, Gg[2], Be[2], 21 * 21, coefA, coefB);
    bn_apply<<<dim3(1, 64, N_TOT), 32>>>(pmax, pmin, coefA, coefB, bufB, 10 * 10);

    // ---- layer 4: 64 -> 64, 10x10 -> pooled 5x5 (features) ----
    conv_fused<64, 10, 5, 5, 32, 16><<<dim3(1, 8, N_TOT), 32>>>(
        bufB, bufB, N_TOT, W[3], Bb[3], pmax, pmin, sums + 768);
    bn_finalize<<<1, 128>>>(sums + 768, Gg[3], Be[3], 10 * 10, coefA, coefB);
    bn_apply<<<dim3(1, 64, N_TOT), 32>>>(pmax, pmin, coefA, coefB, feat, 5 * 5);

    // ---- simplex similarities ----
    volA_kernel<<<40, 128>>>(feat, volA);
    volB_kernel<<<600, 128>>>(feat, volA, out);
}

// round 11
// speedup vs baseline: 2.9640x; 1.0454x over previous
#include <cuda_runtime.h>
#include <cstddef>

#define N_SUP 200
#define N_SMP 120
#define N_TOT 320
#define CH 64
#define EPSBN 1e-5

// ---------------- scratch (device globals; no allocation allowed) ----------
__device__ float  g_bufA[(size_t)N_TOT * CH * 84 * 84];   // carved into pmax/pmin
__device__ float  g_bufB[(size_t)N_TOT * CH * 42 * 42];
__device__ float  g_feat[(size_t)N_TOT * 1600];
__device__ double g_sums[1024];       // 4 layers x [sum(128) | sumsq(128)], zero-init; re-zeroed by bn_finalize
__device__ float  g_coefA[128];
__device__ float  g_coefB[128];
__device__ double g_volA[40];

#define OFF_PMAX ((size_t)0)
#define OFF_PMIN ((size_t)40000000)

// ---------------- f32x2 helpers ---------------------------------------------
__device__ __forceinline__ unsigned long long pk2(float lo, float hi) {
    unsigned long long r;
    asm("mov.b64 %0, {%1, %2};" : "=l"(r)
        : "r"(__float_as_uint(lo)), "r"(__float_as_uint(hi)));
    return r;
}
__device__ __forceinline__ void upk2(unsigned long long p, float& lo, float& hi) {
    unsigned a, b;
    asm("mov.b64 {%0, %1}, %2;" : "=r"(a), "=r"(b) : "l"(p));
    lo = __uint_as_float(a); hi = __uint_as_float(b);
}
__device__ __forceinline__ void fma2(unsigned long long& acc,
                                     unsigned long long w,
                                     unsigned long long v) {
    asm("fma.rn.f32x2 %0, %1, %2, %0;" : "+l"(acc) : "l"(w), "l"(v));
}

// ---------------- fused conv3x3 + ReLU + stats + minmax-pool ----------------
// Thread: 2x2 output pixels x 16 couts (8 f32x2 channel-pairs).
// 16 input values / 16 LDGs amortized over 288 fma2 per ci (was 144).
// Epilogue: 8 passes over cout-pairs with a small sred[4][TPB] buffer.
template<int CIN, int H, int TY, int TX, int TPB, int MINB>
__global__ void __launch_bounds__(TPB, MINB)
conv_fused(const float* __restrict__ in1,     // images [0, split)
           const float* __restrict__ in2,     // images [split, N_TOT)
           int split,
           const float* __restrict__ w,
           const float* __restrict__ bias,
           float* __restrict__ pmax,
           float* __restrict__ pmin,
           double* __restrict__ sums)
{
    constexpr int NPIX = H * H;
    constexpr int HO = H / 2;
    constexpr int NACT = TY * TX;
    constexpr int KT = CIN * 9;
    constexpr int NW = TPB / 32;

    __shared__ __align__(16) float ws[KT * 16];  // [kt][co] co contiguous (16)
    __shared__ float sred[4][TPB];               // per-pass: sum/sq for 2 couts

    const int tid = threadIdx.x;
    const int cog = blockIdx.y;                  // 4 groups of 16 couts
    const int img = blockIdx.z;

    for (int i = tid; i < KT * 16; i += TPB) {
        int co = i / KT, kt = i - co * KT;
        ws[kt * 16 + co] = w[(size_t)(cog * 16 + co) * KT + kt];
    }
    __syncthreads();

    const int ty = tid / TX, tx = tid % TX;
    const int py0 = blockIdx.x * TY + ty;
    const int gy0 = 2 * py0;
    const int gx0 = 2 * tx;
    const bool active = (tid < NACT) && (gy0 < H);

    bool rv[4], cv[4];
#pragma unroll
    for (int r = 0; r < 4; r++) { int yy = gy0 - 1 + r; rv[r] = active && yy >= 0 && yy < H; }
#pragma unroll
    for (int c = 0; c < 4; c++) { int xx = gx0 - 1 + c; cv[c] = active && xx >= 0 && xx < H; }

    const float* base = (img < split) ? (in1 + (size_t)img * CIN * NPIX)
                                      : (in2 + (size_t)(img - split) * CIN * NPIX);
    const float* inp = base + (long)(gy0 - 1) * H + (gx0 - 1);

    unsigned long long acc[8][4];
#pragma unroll
    for (int cp = 0; cp < 8; cp++) {
        unsigned long long bp = pk2(bias[cog * 16 + 2 * cp], bias[cog * 16 + 2 * cp + 1]);
#pragma unroll
        for (int px = 0; px < 4; px++) acc[cp][px] = bp;
    }

    // ---- software-pipelined mainloop ----
    float cur[16];
#pragma unroll
    for (int r = 0; r < 4; r++)
#pragma unroll
        for (int c = 0; c < 4; c++)
            cur[r * 4 + c] = (rv[r] && cv[c]) ? __ldg(inp + r * H + c) : 0.f;

#pragma unroll 2
    for (int ci = 0; ci < CIN; ci++) {
        float nxt[16];
        if (ci + 1 < CIN) {
            const float* icn = inp + (size_t)(ci + 1) * NPIX;
#pragma unroll
            for (int r = 0; r < 4; r++)
#pragma unroll
                for (int c = 0; c < 4; c++)
                    nxt[r * 4 + c] = (rv[r] && cv[c]) ? __ldg(icn + r * H + c) : 0.f;
        }

        unsigned long long ivp[16];
#pragma unroll
        for (int k = 0; k < 16; k++) ivp[k] = pk2(cur[k], cur[k]);

        const float* wk = ws + ci * 144;
#pragma unroll
        for (int ky = 0; ky < 3; ky++)
#pragma unroll
        for (int kx = 0; kx < 3; kx++) {
            const ulonglong2* wp = (const ulonglong2*)(wk + (ky * 3 + kx) * 16);
            ulonglong2 wa = wp[0];
            ulonglong2 wb = wp[1];
            ulonglong2 wc2 = wp[2];
            ulonglong2 wd = wp[3];
#pragma unroll
            for (int py = 0; py < 2; py++)
#pragma unroll
            for (int pxx = 0; pxx < 2; pxx++) {
                unsigned long long v = ivp[(py + ky) * 4 + (pxx + kx)];
                int px = py * 2 + pxx;
                fma2(acc[0][px], wa.x, v);
                fma2(acc[1][px], wa.y, v);
                fma2(acc[2][px], wb.x, v);
                fma2(acc[3][px], wb.y, v);
                fma2(acc[4][px], wc2.x, v);
                fma2(acc[5][px], wc2.y, v);
                fma2(acc[6][px], wd.x, v);
                fma2(acc[7][px], wd.y, v);
            }
        }

#pragma unroll
        for (int k = 0; k < 16; k++) cur[k] = nxt[k];
    }

    bool pv[4];
#pragma unroll
    for (int py = 0; py < 2; py++)
#pragma unroll
        for (int pxx = 0; pxx < 2; pxx++)
            pv[py * 2 + pxx] = active && (gy0 + py) < H && (gx0 + pxx) < H;

    const bool wr = active && py0 < HO && tx < HO;
    const int grp = (img >= N_SUP);
    const int wid = tid >> 5, lid = tid & 31;

    float* pmax_b = pmax + ((size_t)img * CH + cog * 16) * (HO * HO) + py0 * HO + tx;
    float* pmin_b = pmin + ((size_t)img * CH + cog * 16) * (HO * HO) + py0 * HO + tx;

    // 8 passes: one cout-pair per pass through the small sred buffer.
#pragma unroll
    for (int cp = 0; cp < 8; cp++) {
#pragma unroll
        for (int j = 0; j < 2; j++) {
            float r0, r1, r2, r3, t;
            upk2(acc[cp][0], r0, t); if (j) r0 = t;
            upk2(acc[cp][1], r1, t); if (j) r1 = t;
            upk2(acc[cp][2], r2, t); if (j) r2 = t;
            upk2(acc[cp][3], r3, t); if (j) r3 = t;
            r0 = fmaxf(r0, 0.f); r1 = fmaxf(r1, 0.f);
            r2 = fmaxf(r2, 0.f); r3 = fmaxf(r3, 0.f);

            float s0 = pv[0] ? r0 : 0.f, s1 = pv[1] ? r1 : 0.f;
            float s2 = pv[2] ? r2 : 0.f, s3 = pv[3] ? r3 : 0.f;
            sred[j * 2 + 0][tid] = s0 + s1 + s2 + s3;
            sred[j * 2 + 1][tid] = s0 * s0 + s1 * s1 + s2 * s2 + s3 * s3;

            if (wr) {
                int co = cp * 2 + j;
                float mx = fmaxf(fmaxf(r0, r1), fmaxf(r2, r3));
                float mn = fminf(fminf(r0, r1), fminf(r2, r3));
                pmax_b[(size_t)co * HO * HO] = mx;
                pmin_b[(size_t)co * HO * HO] = mn;
            }
        }
        __syncthreads();
        for (int row = wid; row < 4; row += NW) {
            float v = 0.f;
            for (int i = lid; i < TPB; i += 32) v += sred[row][i];
#pragma unroll
            for (int o = 16; o; o >>= 1) v += __shfl_xor_sync(0xffffffffu, v, o);
            if (lid == 0) {
                int j = row >> 1, isq = row & 1;
                int co = cp * 2 + j;
                atomicAdd(&sums[isq * 128 + grp * 64 + cog * 16 + co], (double)v);
            }
        }
        __syncthreads();
    }
}

// ---------------- BN finalize (reads, then re-zeroes its layer's sums) ------
__global__ void bn_finalize(double* __restrict__ sums,
                            const float* __restrict__ g,
                            const float* __restrict__ be,
                            int NPIX,
                            float* __restrict__ coefA,
                            float* __restrict__ coefB)
{
    int i = threadIdx.x;
    if (i >= 128) return;
    int grp = i / 64, c = i % 64;
    double cnt = (double)(grp ? N_SMP : N_SUP) * NPIX;
    double s  = sums[i];
    double s2 = sums[128 + i];
    sums[i] = 0.0;           // re-arm for next graph replay
    sums[128 + i] = 0.0;
    double mean = s / cnt;
    double var  = s2 / cnt - mean * mean;
    double a = (double)g[c] * rsqrt(var + EPSBN);
    coefA[i] = (float)a;
    coefB[i] = (float)((double)be[c] - mean * a);
}

// ---------------- pick pooled value and apply affine BN (MLP=4) -------------
// grid: (ceil(plane/(TPB*4)), channel, image)
__global__ void bn_apply(const float* __restrict__ pmax,
                         const float* __restrict__ pmin,
                         const float* __restrict__ coefA,
                         const float* __restrict__ coefB,
                         float* __restrict__ out,
                         int plane)
{
    int i0 = (blockIdx.x * blockDim.x) * 4 + threadIdx.x;
    int c = blockIdx.y;
    int n = blockIdx.z;
    int grp = (n >= N_SUP);
    float a = coefA[grp * 64 + c], b = coefB[grp * 64 + c];
    size_t bofs = ((size_t)n * CH + c) * plane;
    const float* p = (a > 0.f) ? pmax : pmin;

    float v[4];
    int idx[4];
#pragma unroll
    for (int k = 0; k < 4; k++) {
        idx[k] = i0 + k * blockDim.x;
        v[k] = (idx[k] < plane) ? p[bofs + idx[k]] : 0.f;
    }
#pragma unroll
    for (int k = 0; k < 4; k++)
        if (idx[k] < plane) out[bofs + idx[k]] = fmaf(v[k], a, b);
}

// ---------------- simplex volumes -------------------------------------------
__device__ __forceinline__ double det_elim(double* G, int n)
{
    double det = 1.0;
    for (int k = 0; k < n; k++) {
        double piv = G[k * n + k];
        det *= piv;
        double inv = 1.0 / piv;
        for (int i = k + 1; i < n; i++) {
            double f = G[i * n + k] * inv;
            for (int j = k + 1; j < n; j++) G[i * n + j] -= f * G[k * n + j];
        }
    }
    return det;
}

__global__ void volA_kernel(const float* __restrict__ feat, double* __restrict__ volA)
{
    int bw = blockIdx.x;
    int b = bw / 5, w = bw % 5;
    const float* base = feat + ((size_t)(b * 25 + w * 5)) * 1600;

    double acc[10];
#pragma unroll
    for (int k = 0; k < 10; k++) acc[k] = 0.0;

    for (int d = threadIdx.x; d < 1600; d += blockDim.x) {
        float s0 = base[d];
        float a[4];
        a[0] = base[1600 + d] - s0;
        a[1] = base[3200 + d] - s0;
        a[2] = base[4800 + d] - s0;
        a[3] = base[6400 + d] - s0;
        int k = 0;
#pragma unroll
        for (int i = 0; i < 4; i++)
#pragma unroll
            for (int j = i; j < 4; j++)
                acc[k++] += (double)a[i] * a[j];
    }
    __shared__ double sh[128];
    __shared__ double Gp[10];
    int tid = threadIdx.x;
    for (int k = 0; k < 10; k++) {
        sh[tid] = acc[k]; __syncthreads();
        for (int r = 64; r > 0; r >>= 1) { if (tid < r) sh[tid] += sh[tid + r]; __syncthreads(); }
        if (tid == 0) Gp[k] = sh[0];
        __syncthreads();
    }
    if (tid == 0) {
        double G[16];
        int k = 0;
        for (int i = 0; i < 4; i++)
            for (int j = i; j < 4; j++) { G[i * 4 + j] = Gp[k]; G[j * 4 + i] = Gp[k]; k++; }
        volA[bw] = det_elim(G, 4);
    }
}

__global__ void volB_kernel(const float* __restrict__ feat,
                            const double* __restrict__ volA,
                            float* __restrict__ out)
{
    int bx = blockIdx.x;
    int w = bx % 5;
    int q = (bx / 5) % 15;
    int b = bx / 75;
    const float* sm = feat + ((size_t)(N_SUP + b * 15 + q)) * 1600;
    const float* s0 = feat + ((size_t)(b * 25 + w * 5)) * 1600;

    double acc[15];
#pragma unroll
    for (int k = 0; k < 15; k++) acc[k] = 0.0;

    for (int d = threadIdx.x; d < 1600; d += blockDim.x) {
        float sv = sm[d];
        float r[5];
#pragma unroll
        for (int s = 0; s < 5; s++) r[s] = s0[(size_t)s * 1600 + d] - sv;
        int k = 0;
#pragma unroll
        for (int i = 0; i < 5; i++)
#pragma unroll
            for (int j = i; j < 5; j++)
                acc[k++] += (double)r[i] * r[j];
    }
    __shared__ double sh[128];
    __shared__ double Gp[15];
    int tid = threadIdx.x;
    for (int k = 0; k < 15; k++) {
        sh[tid] = acc[k]; __syncthreads();
        for (int r = 64; r > 0; r >>= 1) { if (tid < r) sh[tid] += sh[tid + r]; __syncthreads(); }
        if (tid == 0) Gp[k] = sh[0];
        __syncthreads();
    }
    if (tid == 0) {
        double G[25];
        int k = 0;
        for (int i = 0; i < 5; i++)
            for (int j = i; j < 5; j++) { G[i * 5 + j] = Gp[k]; G[j * 5 + i] = Gp[k]; k++; }
        double detB = det_elim(G, 5);
        out[bx] = (float)(-(detB / volA[b * 5 + w]));
    }
}

// ---------------- host orchestration ----------------------------------------
extern "C" void kernel_launch(void* const* d_in, const int* in_sizes, int n_in,
                              void* d_out, int out_size)
{
    const float* sup = (const float*)d_in[0];
    const float* smp = (const float*)d_in[2];
    const float* W[4]  = {(const float*)d_in[3],  (const float*)d_in[7],
                          (const float*)d_in[11], (const float*)d_in[15]};
    const float* Bb[4] = {(const float*)d_in[4],  (const float*)d_in[8],
                          (const float*)d_in[12], (const float*)d_in[16]};
    const float* Gg[4] = {(const float*)d_in[5],  (const float*)d_in[9],
                          (const float*)d_in[13], (const float*)d_in[17]};
    const float* Be[4] = {(const float*)d_in[6],  (const float*)d_in[10],
                          (const float*)d_in[14], (const float*)d_in[18]};
    float* out = (float*)d_out;

    float  *bufA, *bufB, *feat, *coefA, *coefB;
    double *sums, *volA;
    cudaGetSymbolAddress((void**)&bufA,  g_bufA);
    cudaGetSymbolAddress((void**)&bufB,  g_bufB);
    cudaGetSymbolAddress((void**)&feat,  g_feat);
    cudaGetSymbolAddress((void**)&sums,  g_sums);
    cudaGetSymbolAddress((void**)&coefA, g_coefA);
    cudaGetSymbolAddress((void**)&coefB, g_coefB);
    cudaGetSymbolAddress((void**)&volA,  g_volA);

    float* pmax = bufA + OFF_PMAX;
    float* pmin = bufA + OFF_PMIN;

    // ---- layer 1: 3 -> 64, 84x84 -> pooled 42x42 ----  (#1,#2,#3)
    conv_fused<3, 84, 6, 42, 256, 2><<<dim3(7, 4, N_TOT), 256>>>(
        sup, smp, N_SUP, W[0], Bb[0], pmax, pmin, sums + 0);
    bn_finalize<<<1, 128>>>(sums + 0, Gg[0], Be[0], 84 * 84, coefA, coefB);
    bn_apply<<<dim3(2, 64, N_TOT), 256>>>(pmax, pmin, coefA, coefB, bufB, 42 * 42);

    // ---- layer 2: 64 -> 64, 42x42 -> pooled 21x21 ----  (#4 = ncu capture slot)
    conv_fused<64, 42, 21, 21, 448, 1><<<dim3(1, 4, N_TOT), 448>>>(
        bufB, bufB, N_TOT, W[1], Bb[1], pmax, pmin, sums + 256);
    bn_finalize<<<1, 128>>>(sums + 256, Gg[1], Be[1], 42 * 42, coefA, coefB);
    bn_apply<<<dim3(1, 64, N_TOT), 128>>>(pmax, pmin, coefA, coefB, bufB, 21 * 21);

    // ---- layer 3: 64 -> 64, 21x21 -> pooled 10x10 ----
    conv_fused<64, 21, 11, 11, 128, 3><<<dim3(1, 4, N_TOT), 128>>>(
        bufB, bufB, N_TOT, W[2], Bb[2], pmax, pmin, sums + 512);
    bn_finalize<<<1, 128>>>(sums + 512, Gg[2], Be[2], 21 * 21, coefA, coefB);
    bn_apply<<<dim3(1, 64, N_TOT), 32>>>(pmax, pmin, coefA, coefB, bufB, 10 * 10);

    // ---- layer 4: 64 -> 64, 10x10 -> pooled 5x5 (features) ----
    conv_fused<64, 10, 5, 5, 32, 8><<<dim3(1, 4, N_TOT), 32>>>(
        bufB, bufB, N_TOT, W[3], Bb[3], pmax, pmin, sums + 768);
    bn_finalize<<<1, 128>>>(sums + 768, Gg[3], Be[3], 10 * 10, coefA, coefB);
    bn_apply<<<dim3(1, 64, N_TOT), 32>>>(pmax, pmin, coefA, coefB, feat, 5 * 5);

    // ---- simplex similarities ----
    volA_kernel<<<40, 128>>>(feat, volA);
    volB_kernel<<<600, 128>>>(feat, volA, out);
}